// round 1
// baseline (speedup 1.0000x reference)
#include <cuda_runtime.h>
#include <cstdint>
#include <cstddef>

#define B_    4
#define S_    512
#define D_    768
#define H_    12
#define HD_   64
#define NRELV 101

// ---------------- scratch (static device allocations, no cudaMalloc) -----------
__device__ float g_q[B_*H_*S_*HD_];
__device__ float g_k[B_*H_*S_*HD_];
__device__ float g_v[B_*H_*S_*HD_];
__device__ float g_bias[(size_t)B_*H_*S_*NRELV];
__device__ float g_ctx[(size_t)B_*S_*D_];
__device__ int   g_arc_is64;

// ---------------- graph_arc dtype detection (int32 vs int64) -------------------
__global__ void detect_kernel(const int* __restrict__ arc32)
{
    __shared__ int cnt;
    if (threadIdx.x == 0) cnt = 0;
    __syncthreads();
    int local = 0;
    for (int i = threadIdx.x; i < 1024; i += blockDim.x)
        if (arc32[2*i + 1] != 0) local++;
    if (local) atomicAdd(&cnt, local);
    __syncthreads();
    if (threadIdx.x == 0) g_arc_is64 = (cnt == 0) ? 1 : 0;
}

__device__ __forceinline__ int arc_at(const void* arc, int is64, size_t idx)
{
    if (is64) return (int)(((const long long*)arc)[idx]);
    return ((const int*)arc)[idx];
}

// ---------------- SGEMM: out[m,n] = sum_k X[m,k]*W[n,k] + bias[n] --------------
// BM=128, BN=64, BK=16, 256 threads, 8x4 micro-tile. MODE 0: scatter to
// (b,h,s,e) scratch layout; MODE 1: plain row-major (B*S, D).
template<int MODE>
__global__ void __launch_bounds__(256)
sgemm_kernel(const float* __restrict__ X, const float* __restrict__ W,
             const float* __restrict__ bias, float* __restrict__ out)
{
    __shared__ float As[16][132];
    __shared__ float Bs[16][68];
    const int tid = threadIdx.x;
    const int tx  = tid & 15;
    const int ty  = tid >> 4;
    const int m0  = blockIdx.y * 128;
    const int n0  = blockIdx.x * 64;

    float acc[8][4];
    #pragma unroll
    for (int i = 0; i < 8; i++)
        #pragma unroll
        for (int j = 0; j < 4; j++) acc[i][j] = 0.f;

    for (int k0 = 0; k0 < D_; k0 += 16) {
        #pragma unroll
        for (int u = 0; u < 2; u++) {
            int f   = tid*2 + u;
            int row = f >> 2;
            int c4  = (f & 3) << 2;
            float4 v = *(const float4*)(X + (size_t)(m0 + row)*D_ + k0 + c4);
            As[c4+0][row] = v.x; As[c4+1][row] = v.y;
            As[c4+2][row] = v.z; As[c4+3][row] = v.w;
        }
        {
            int n  = tid >> 2;
            int c4 = (tid & 3) << 2;
            float4 v = *(const float4*)(W + (size_t)(n0 + n)*D_ + k0 + c4);
            Bs[c4+0][n] = v.x; Bs[c4+1][n] = v.y;
            Bs[c4+2][n] = v.z; Bs[c4+3][n] = v.w;
        }
        __syncthreads();
        #pragma unroll
        for (int k = 0; k < 16; k++) {
            float4 a0 = *(const float4*)&As[k][ty*8];
            float4 a1 = *(const float4*)&As[k][ty*8 + 4];
            float4 b0 = *(const float4*)&Bs[k][tx*4];
            float a[8] = {a0.x,a0.y,a0.z,a0.w,a1.x,a1.y,a1.z,a1.w};
            float bb[4] = {b0.x,b0.y,b0.z,b0.w};
            #pragma unroll
            for (int i = 0; i < 8; i++)
                #pragma unroll
                for (int j = 0; j < 4; j++) acc[i][j] += a[i]*bb[j];
        }
        __syncthreads();
    }

    #pragma unroll
    for (int i = 0; i < 8; i++) {
        int m = m0 + ty*8 + i;
        int b = m >> 9, s = m & (S_-1);
        #pragma unroll
        for (int j = 0; j < 4; j++) {
            int col = n0 + tx*4 + j;
            float val = acc[i][j] + bias[col];
            if (MODE == 0) {
                int hh = col >> 6, e = col & 63;
                out[(((size_t)(b*H_ + hh)*S_ + s) << 6) + e] = val;
            } else {
                out[(size_t)m*D_ + col] = val;
            }
        }
    }
}

// ---------------- bias table: bias[b,h,s,rel] = q_s.Ek[rel] + k_s.Eq[rel] ------
// CTA = (b, h, 32 s-rows). sE stored transposed [128 dims][104 rels] so the
// inner loop reads float4 along rel (conflict-free).
__global__ void __launch_bounds__(256)
bias_kernel(const float* __restrict__ Ek, const float* __restrict__ Eq)
{
    extern __shared__ float sm[];
    float* sE  = sm;              // [128][104]
    float* sQK = sm + 128*104;    // [32][128]  (q | k per row)
    const int b  = blockIdx.z, h = blockIdx.y, s0 = blockIdx.x * 32;
    const int tid = threadIdx.x;

    for (int i = tid; i < NRELV*HD_; i += 256) {
        int rel = i >> 6, e = i & 63;
        sE[e*104 + rel]        = Ek[i];
        sE[(64 + e)*104 + rel] = Eq[i];
    }
    if (tid < 128) {
        sE[tid*104 + 101] = 0.f; sE[tid*104 + 102] = 0.f; sE[tid*104 + 103] = 0.f;
    }
    const size_t base = ((size_t)(b*H_ + h)*S_ + s0)*HD_;
    for (int i = tid; i < 32*64; i += 256) {
        int r = i >> 6, e = i & 63;
        sQK[r*128 + e]      = g_q[base + i];
        sQK[r*128 + 64 + e] = g_k[base + i];
    }
    __syncthreads();

    const size_t ob = ((size_t)(b*H_ + h)*S_ + s0)*NRELV;
    for (int c = tid; c < 16*26; c += 256) {
        int r0 = (c / 26) * 2;
        int rg = (c % 26) * 4;
        float acc0[4] = {0,0,0,0}, acc1[4] = {0,0,0,0};
        const float* q0p = &sQK[r0*128];
        const float* q1p = &sQK[(r0+1)*128];
        #pragma unroll 4
        for (int d = 0; d < 128; d++) {
            float q0 = q0p[d], q1 = q1p[d];
            float4 ev = *(const float4*)&sE[d*104 + rg];
            acc0[0] += q0*ev.x; acc0[1] += q0*ev.y;
            acc0[2] += q0*ev.z; acc0[3] += q0*ev.w;
            acc1[0] += q1*ev.x; acc1[1] += q1*ev.y;
            acc1[2] += q1*ev.z; acc1[3] += q1*ev.w;
        }
        #pragma unroll
        for (int j = 0; j < 4; j++) {
            if (rg + j < NRELV) {
                g_bias[ob + (size_t)r0*NRELV + rg + j]     = acc0[j];
                g_bias[ob + (size_t)(r0+1)*NRELV + rg + j] = acc1[j];
            }
        }
    }
}

// ---------------- fused attention -------------------------------------------
// CTA = (b, h, 16 query rows). scores in shared, K/V streamed 128x64 (stride 68
// to avoid bank conflicts), softmax in-place, relation binning via shared
// atomics, PV + wrel@Ev + 1/Z fused. Writes context in (B,S,D) layout.
__global__ void __launch_bounds__(256)
attn_kernel(const int* __restrict__ mask, const void* __restrict__ arc,
            const float* __restrict__ Ev)
{
    extern __shared__ float sm[];
    float* sS    = sm;               // 16*512           = 8192
    float* sKV   = sm + 8192;        // 128*68           = 8704
    float* sQ    = sKV + 8704;       // 16*64 (also ctx) = 1024
    float* sB    = sQ + 1024;        // 16*101           = 1616
    float* sW    = sB + 1616;        // 16*101           = 1616
    float* sZ    = sW + 1616;        // 16
    int*   sMask = (int*)(sZ + 16);  // 512

    const int qt = blockIdx.x, h = blockIdx.y, b = blockIdx.z;
    const int i0 = qt * 16;
    const int tid = threadIdx.x;
    const int is64 = g_arc_is64;
    const size_t bh     = (size_t)b*H_ + h;
    const size_t qbase  = (bh*S_ + i0)*HD_;
    const size_t kvbase = bh*S_*HD_;

    for (int i = tid; i < 16*HD_; i += 256) sQ[i] = g_q[qbase + i];
    for (int i = tid; i < 16*NRELV; i += 256) {
        sB[i] = g_bias[(bh*S_ + i0)*NRELV + i];
        sW[i] = 0.f;
    }
    for (int i = tid; i < S_; i += 256) sMask[i] = mask[b*S_ + i];
    __syncthreads();

    // ---- pass 1: raw scores q.k ----
    const int ig = tid >> 6;     // row group (4 rows)
    const int jl = tid & 63;     // handles j = jl and jl+64 within a 128-tile
    for (int jt = 0; jt < 4; jt++) {
        const int j0 = jt * 128;
        for (int f = tid; f < 2048; f += 256) {
            int row = f >> 4, c = (f & 15) << 2;
            *(float4*)&sKV[row*68 + c] =
                *(const float4*)&g_k[kvbase + (size_t)(j0 + row)*HD_ + c];
        }
        __syncthreads();
        float acc0[4] = {0,0,0,0}, acc1[4] = {0,0,0,0};
        #pragma unroll
        for (int d = 0; d < 64; d += 4) {
            float4 k0 = *(const float4*)&sKV[jl*68 + d];
            float4 k1 = *(const float4*)&sKV[(jl + 64)*68 + d];
            #pragma unroll
            for (int r = 0; r < 4; r++) {
                float4 q = *(const float4*)&sQ[(ig*4 + r)*64 + d];
                acc0[r] += q.x*k0.x + q.y*k0.y + q.z*k0.z + q.w*k0.w;
                acc1[r] += q.x*k1.x + q.y*k1.y + q.z*k1.z + q.w*k1.w;
            }
        }
        #pragma unroll
        for (int r = 0; r < 4; r++) {
            sS[(ig*4 + r)*S_ + j0 + jl]      = acc0[r];
            sS[(ig*4 + r)*S_ + j0 + 64 + jl] = acc1[r];
        }
        __syncthreads();
    }

    // ---- relation bias + scale + mask ----
    const size_t arcbase = ((size_t)b*S_ + i0)*S_;
    for (int idx = tid; idx < 16*S_; idx += 256) {
        int i = idx >> 9, j = idx & (S_-1);
        int rel = arc_at(arc, is64, arcbase + (size_t)i*S_ + j);
        float s = (sS[idx] + sB[i*NRELV + rel]) * 0.125f;
        if (sMask[j] == 0) s = -1e30f;
        sS[idx] = s;
    }
    __syncthreads();

    // ---- softmax (unnormalized exp; Z per row) ----
    const int wrp = tid >> 5, lane = tid & 31;
    #pragma unroll
    for (int rr = 0; rr < 2; rr++) {
        int row = wrp*2 + rr;
        float m = -3.4e38f;
        for (int j = lane; j < S_; j += 32) m = fmaxf(m, sS[row*S_ + j]);
        #pragma unroll
        for (int o = 16; o; o >>= 1) m = fmaxf(m, __shfl_xor_sync(0xffffffffu, m, o));
        float z = 0.f;
        for (int j = lane; j < S_; j += 32) {
            float p = __expf(sS[row*S_ + j] - m);
            sS[row*S_ + j] = p;
            z += p;
        }
        #pragma unroll
        for (int o = 16; o; o >>= 1) z += __shfl_xor_sync(0xffffffffu, z, o);
        if (lane == 0) sZ[row] = z;
    }
    __syncthreads();

    // ---- relation binning: wrel[i,rel] += p[i,j] ----
    for (int idx = tid; idx < 16*S_; idx += 256) {
        int i = idx >> 9, j = idx & (S_-1);
        int rel = arc_at(arc, is64, arcbase + (size_t)i*S_ + j);
        atomicAdd(&sW[i*NRELV + rel], sS[idx]);
    }
    for (int i = tid; i < 1024; i += 256) sQ[i] = 0.f;   // sQ becomes sCtx
    __syncthreads();

    // ---- pass 2: context = p @ V (j split 4-way across thread groups) ----
    const int jq  = tid >> 6;
    const int t64 = tid & 63;
    const int rg  = (t64 >> 4) << 2;   // 4 rows
    const int e0  = (t64 & 15) << 2;   // 4 cols
    float acc[4][4];
    #pragma unroll
    for (int r = 0; r < 4; r++)
        #pragma unroll
        for (int c2 = 0; c2 < 4; c2++) acc[r][c2] = 0.f;

    for (int jt = 0; jt < 4; jt++) {
        for (int f = tid; f < 2048; f += 256) {
            int row = f >> 4, c = (f & 15) << 2;
            *(float4*)&sKV[row*68 + c] =
                *(const float4*)&g_v[kvbase + (size_t)(jt*128 + row)*HD_ + c];
        }
        __syncthreads();
        #pragma unroll 4
        for (int jj = 0; jj < 32; jj++) {
            int jlv = jq*32 + jj;
            int j   = jt*128 + jlv;
            float4 v = *(const float4*)&sKV[jlv*68 + e0];
            #pragma unroll
            for (int r = 0; r < 4; r++) {
                float p = sS[(rg + r)*S_ + j];
                acc[r][0] += p*v.x; acc[r][1] += p*v.y;
                acc[r][2] += p*v.z; acc[r][3] += p*v.w;
            }
        }
        __syncthreads();
    }
    #pragma unroll
    for (int r = 0; r < 4; r++) {
        atomicAdd(&sQ[(rg+r)*64 + e0 + 0], acc[r][0]);
        atomicAdd(&sQ[(rg+r)*64 + e0 + 1], acc[r][1]);
        atomicAdd(&sQ[(rg+r)*64 + e0 + 2], acc[r][2]);
        atomicAdd(&sQ[(rg+r)*64 + e0 + 3], acc[r][3]);
    }

    // ---- + wrel @ Ev, normalize by 1/Z, store ----
    for (int i = tid; i < NRELV*HD_; i += 256) sKV[i] = Ev[i];
    __syncthreads();

    const int e  = tid & 63;
    const int r0 = (tid >> 6) * 4;
    float cv[4] = {0,0,0,0};
    for (int rel = 0; rel < NRELV; rel++) {
        float ev = sKV[rel*64 + e];
        #pragma unroll
        for (int r = 0; r < 4; r++) cv[r] += sW[(r0 + r)*NRELV + rel] * ev;
    }
    #pragma unroll
    for (int r = 0; r < 4; r++) {
        int row = r0 + r;
        float val = (sQ[row*64 + e] + cv[r]) / sZ[row];
        g_ctx[((size_t)b*S_ + i0 + row)*D_ + h*HD_ + e] = val;
    }
}

// ---------------- launch ------------------------------------------------------
extern "C" void kernel_launch(void* const* d_in, const int* in_sizes, int n_in,
                              void* d_out, int out_size)
{
    (void)in_sizes; (void)n_in; (void)out_size;
    const float* query = (const float*)d_in[0];
    const float* key_  = (const float*)d_in[1];
    const float* value = (const float*)d_in[2];
    const int*   mask  = (const int*)d_in[3];
    const void*  arc   = d_in[4];
    const float* Wq = (const float*)d_in[5];
    const float* bq = (const float*)d_in[6];
    const float* Wk = (const float*)d_in[7];
    const float* bk = (const float*)d_in[8];
    const float* Wv = (const float*)d_in[9];
    const float* bv = (const float*)d_in[10];
    const float* Wo = (const float*)d_in[11];
    const float* bo = (const float*)d_in[12];
    const float* Ek = (const float*)d_in[13];
    const float* Eq = (const float*)d_in[14];
    const float* Ev = (const float*)d_in[15];
    float* out = (float*)d_out;

    const size_t smem2 = (size_t)(128*104 + 32*128) * sizeof(float);
    const size_t smem3 = (size_t)(8192 + 8704 + 1024 + 1616 + 1616 + 16) * sizeof(float)
                       + 512 * sizeof(int);
    cudaFuncSetAttribute(bias_kernel, cudaFuncAttributeMaxDynamicSharedMemorySize, (int)smem2);
    cudaFuncSetAttribute(attn_kernel, cudaFuncAttributeMaxDynamicSharedMemorySize, (int)smem3);

    float *gq, *gk, *gv, *gctx;
    cudaGetSymbolAddress((void**)&gq,   g_q);
    cudaGetSymbolAddress((void**)&gk,   g_k);
    cudaGetSymbolAddress((void**)&gv,   g_v);
    cudaGetSymbolAddress((void**)&gctx, g_ctx);

    detect_kernel<<<1, 256>>>((const int*)arc);

    dim3 gemmGrid(D_/64, (B_*S_)/128);   // (12, 16)
    sgemm_kernel<0><<<gemmGrid, 256>>>(query, Wq, bq, gq);
    sgemm_kernel<0><<<gemmGrid, 256>>>(key_,  Wk, bk, gk);
    sgemm_kernel<0><<<gemmGrid, 256>>>(value, Wv, bv, gv);

    bias_kernel<<<dim3(S_/32, H_, B_), 256, smem2>>>(Ek, Eq);
    attn_kernel<<<dim3(S_/16, H_, B_), 256, smem3>>>(mask, arc, Ev);

    sgemm_kernel<1><<<gemmGrid, 256>>>(gctx, Wo, bo, out);
}

// round 2
// speedup vs baseline: 2.3797x; 2.3797x over previous
#include <cuda_runtime.h>
#include <cuda_bf16.h>
#include <cstdint>
#include <cstddef>

#define B_    4
#define S_    512
#define D_    768
#define H_    12
#define HD_   64
#define NRELV 101

#define BM    128
#define BN    128
#define BK    32
#define LDSB  40      // padded bf16 stride (80 bytes) -> ldmatrix conflict-free

// ---------------- scratch (static device allocations, no cudaMalloc) -----------
__device__ float g_q[B_*H_*S_*HD_];
__device__ float g_k[B_*H_*S_*HD_];
__device__ float g_v[B_*H_*S_*HD_];
__device__ float g_bias[(size_t)B_*H_*S_*NRELV];
__device__ float g_ctx[(size_t)B_*S_*D_];
__device__ int   g_arc_is64;

// ---------------- graph_arc dtype detection (int32 vs int64) -------------------
__global__ void detect_kernel(const int* __restrict__ arc32)
{
    __shared__ int cnt;
    if (threadIdx.x == 0) cnt = 0;
    __syncthreads();
    int local = 0;
    for (int i = threadIdx.x; i < 1024; i += blockDim.x)
        if (arc32[2*i + 1] != 0) local++;
    if (local) atomicAdd(&cnt, local);
    __syncthreads();
    if (threadIdx.x == 0) g_arc_is64 = (cnt == 0) ? 1 : 0;
}

__device__ __forceinline__ int arc_at(const void* arc, int is64, size_t idx)
{
    if (is64) return (int)(((const long long*)arc)[idx]);
    return ((const int*)arc)[idx];
}

// ---------------- tensor-core GEMM (bf16x3 split, fp32 accuracy) ---------------
// C[m,n] = sum_k X[m,k] * W[n,k] + bias[n]
// MODE 0: QKV fused via blockIdx.z, scatter to (b,h,s,e). MODE 1: row-major out.
struct GemmArgs {
    const float* X[3];
    const float* W[3];
    const float* b[3];
    float*       o[3];
};

__device__ __forceinline__ void ldsm_x4(uint32_t addr, uint32_t& r0, uint32_t& r1,
                                        uint32_t& r2, uint32_t& r3)
{
    asm volatile("ldmatrix.sync.aligned.m8n8.x4.shared.b16 {%0,%1,%2,%3}, [%4];"
                 : "=r"(r0), "=r"(r1), "=r"(r2), "=r"(r3) : "r"(addr));
}

__device__ __forceinline__ void mma16816(float* c, const uint32_t* a,
                                         uint32_t b0, uint32_t b1)
{
    asm volatile(
        "mma.sync.aligned.m16n8k16.row.col.f32.bf16.bf16.f32 "
        "{%0,%1,%2,%3}, {%4,%5,%6,%7}, {%8,%9}, {%0,%1,%2,%3};"
        : "+f"(c[0]), "+f"(c[1]), "+f"(c[2]), "+f"(c[3])
        : "r"(a[0]), "r"(a[1]), "r"(a[2]), "r"(a[3]), "r"(b0), "r"(b1));
}

__device__ __forceinline__ void split_store(__nv_bfloat16* hi, __nv_bfloat16* lo,
                                            float4 v)
{
    float f[4] = {v.x, v.y, v.z, v.w};
    unsigned short hs[4], ls[4];
    #pragma unroll
    for (int j = 0; j < 4; j++) {
        __nv_bfloat16 h = __float2bfloat16(f[j]);
        __nv_bfloat16 l = __float2bfloat16(f[j] - __bfloat162float(h));
        hs[j] = *(unsigned short*)&h;
        ls[j] = *(unsigned short*)&l;
    }
    uint2 uh, ul;
    uh.x = (uint32_t)hs[0] | ((uint32_t)hs[1] << 16);
    uh.y = (uint32_t)hs[2] | ((uint32_t)hs[3] << 16);
    ul.x = (uint32_t)ls[0] | ((uint32_t)ls[1] << 16);
    ul.y = (uint32_t)ls[2] | ((uint32_t)ls[3] << 16);
    *(uint2*)hi = uh;
    *(uint2*)lo = ul;
}

template<int MODE>
__global__ void __launch_bounds__(256, 1)
mma_gemm_kernel(GemmArgs args)
{
    __shared__ __nv_bfloat16 sXhi[BM][LDSB], sXlo[BM][LDSB];
    __shared__ __nv_bfloat16 sWhi[BN][LDSB], sWlo[BN][LDSB];

    const int z = (MODE == 0) ? blockIdx.z : 0;
    const float* __restrict__ X    = args.X[z];
    const float* __restrict__ W    = args.W[z];
    const float* __restrict__ bias = args.b[z];
    float*       __restrict__ out  = args.o[z];

    const int tid  = threadIdx.x;
    const int lane = tid & 31;
    const int warp = tid >> 5;
    const int wm   = warp & 3;     // 4 warps along M (32 rows each)
    const int wn   = warp >> 2;    // 2 warps along N (64 cols each)
    const int m0   = blockIdx.y * BM;
    const int n0   = blockIdx.x * BN;

    float acc[2][8][4];
    #pragma unroll
    for (int mt = 0; mt < 2; mt++)
        #pragma unroll
        for (int nt = 0; nt < 8; nt++)
            #pragma unroll
            for (int j = 0; j < 4; j++) acc[mt][nt][j] = 0.f;

    // ldmatrix source lane mapping
    const int mat = lane >> 3, mr = lane & 7;
    // A: mat0 rows0-7 k0 | mat1 rows8-15 k0 | mat2 rows0-7 k8 | mat3 rows8-15 k8
    const int a_row = (mat & 1) * 8 + mr;
    const int a_k   = (mat >> 1) * 8;
    const uint32_t aHi = (uint32_t)__cvta_generic_to_shared(&sXhi[wm*32 + a_row][a_k]);
    const uint32_t aLo = (uint32_t)__cvta_generic_to_shared(&sXlo[wm*32 + a_row][a_k]);
    // B: mat0 n0-7 k0 | mat1 n0-7 k8 | mat2 n8-15 k0 | mat3 n8-15 k8
    const int b_row = (mat >> 1) * 8 + mr;
    const int b_k   = (mat & 1) * 8;
    const uint32_t bHi = (uint32_t)__cvta_generic_to_shared(&sWhi[wn*64 + b_row][b_k]);
    const uint32_t bLo = (uint32_t)__cvta_generic_to_shared(&sWlo[wn*64 + b_row][b_k]);

    const int ldrow = tid >> 3;        // 0..31 (+32*i)
    const int ldseg = (tid & 7) * 4;   // col within BK

    for (int k0 = 0; k0 < D_; k0 += BK) {
        float4 xv[4], wv[4];
        #pragma unroll
        for (int i = 0; i < 4; i++) {
            int row = ldrow + i*32;
            xv[i] = *(const float4*)(X + (size_t)(m0 + row)*D_ + k0 + ldseg);
            wv[i] = *(const float4*)(W + (size_t)(n0 + row)*D_ + k0 + ldseg);
        }
        __syncthreads();
        #pragma unroll
        for (int i = 0; i < 4; i++) {
            int row = ldrow + i*32;
            split_store(&sXhi[row][ldseg], &sXlo[row][ldseg], xv[i]);
            split_store(&sWhi[row][ldseg], &sWlo[row][ldseg], wv[i]);
        }
        __syncthreads();

        #pragma unroll
        for (int ks = 0; ks < 2; ks++) {
            const uint32_t ko = ks * 32;              // 16 bf16 = 32 bytes
            uint32_t ah[2][4], al[2][4];
            #pragma unroll
            for (int mt = 0; mt < 2; mt++) {
                const uint32_t mo = mt * (16 * LDSB * 2);
                ldsm_x4(aHi + mo + ko, ah[mt][0], ah[mt][1], ah[mt][2], ah[mt][3]);
                ldsm_x4(aLo + mo + ko, al[mt][0], al[mt][1], al[mt][2], al[mt][3]);
            }
            #pragma unroll
            for (int pr = 0; pr < 4; pr++) {
                const uint32_t po = pr * (16 * LDSB * 2);
                uint32_t bh[4], bl[4];
                ldsm_x4(bHi + po + ko, bh[0], bh[1], bh[2], bh[3]);
                ldsm_x4(bLo + po + ko, bl[0], bl[1], bl[2], bl[3]);
                #pragma unroll
                for (int h2 = 0; h2 < 2; h2++) {
                    const int nt = pr*2 + h2;
                    const uint32_t B0h = bh[h2*2], B1h = bh[h2*2+1];
                    const uint32_t B0l = bl[h2*2], B1l = bl[h2*2+1];
                    #pragma unroll
                    for (int mt = 0; mt < 2; mt++) {
                        mma16816(acc[mt][nt], ah[mt], B0h, B1h);   // hi*hi
                        mma16816(acc[mt][nt], ah[mt], B0l, B1l);   // hi*lo
                        mma16816(acc[mt][nt], al[mt], B0h, B1h);   // lo*hi
                    }
                }
            }
        }
    }

    // ---- epilogue ----
    const int gid = lane >> 2, tig = lane & 3;
    float bcol[8][2];
    #pragma unroll
    for (int nt = 0; nt < 8; nt++) {
        int col = n0 + wn*64 + nt*8 + tig*2;
        bcol[nt][0] = bias[col];
        bcol[nt][1] = bias[col + 1];
    }
    #pragma unroll
    for (int mt = 0; mt < 2; mt++) {
        const int rbase = m0 + wm*32 + mt*16 + gid;
        #pragma unroll
        for (int nt = 0; nt < 8; nt++) {
            const int col = n0 + wn*64 + nt*8 + tig*2;
            float v00 = acc[mt][nt][0] + bcol[nt][0];
            float v01 = acc[mt][nt][1] + bcol[nt][1];
            float v10 = acc[mt][nt][2] + bcol[nt][0];
            float v11 = acc[mt][nt][3] + bcol[nt][1];
            if (MODE == 0) {
                const int hh = col >> 6, e = col & 63;
                int r = rbase;
                int b = r >> 9, s = r & (S_-1);
                size_t o = (((size_t)(b*H_ + hh)*S_ + s) << 6) + e;
                out[o] = v00; out[o + 1] = v01;
                r = rbase + 8; b = r >> 9; s = r & (S_-1);
                o = (((size_t)(b*H_ + hh)*S_ + s) << 6) + e;
                out[o] = v10; out[o + 1] = v11;
            } else {
                out[(size_t)rbase*D_ + col]       = v00;
                out[(size_t)rbase*D_ + col + 1]   = v01;
                out[(size_t)(rbase+8)*D_ + col]   = v10;
                out[(size_t)(rbase+8)*D_ + col+1] = v11;
            }
        }
    }
}

// ---------------- bias table: bias[b,h,s,rel] = q_s.Ek[rel] + k_s.Eq[rel] ------
__global__ void __launch_bounds__(256)
bias_kernel(const float* __restrict__ Ek, const float* __restrict__ Eq)
{
    extern __shared__ float sm[];
    float* sE  = sm;              // [128][104]
    float* sQK = sm + 128*104;    // [32][128]
    const int b  = blockIdx.z, h = blockIdx.y, s0 = blockIdx.x * 32;
    const int tid = threadIdx.x;

    for (int i = tid; i < NRELV*HD_; i += 256) {
        int rel = i >> 6, e = i & 63;
        sE[e*104 + rel]        = Ek[i];
        sE[(64 + e)*104 + rel] = Eq[i];
    }
    if (tid < 128) {
        sE[tid*104 + 101] = 0.f; sE[tid*104 + 102] = 0.f; sE[tid*104 + 103] = 0.f;
    }
    const size_t base = ((size_t)(b*H_ + h)*S_ + s0)*HD_;
    for (int i = tid; i < 32*64; i += 256) {
        int r = i >> 6, e = i & 63;
        sQK[r*128 + e]      = g_q[base + i];
        sQK[r*128 + 64 + e] = g_k[base + i];
    }
    __syncthreads();

    const size_t ob = ((size_t)(b*H_ + h)*S_ + s0)*NRELV;
    for (int c = tid; c < 16*26; c += 256) {
        int r0 = (c / 26) * 2;
        int rg = (c % 26) * 4;
        float acc0[4] = {0,0,0,0}, acc1[4] = {0,0,0,0};
        const float* q0p = &sQK[r0*128];
        const float* q1p = &sQK[(r0+1)*128];
        #pragma unroll 4
        for (int d = 0; d < 128; d++) {
            float q0 = q0p[d], q1 = q1p[d];
            float4 ev = *(const float4*)&sE[d*104 + rg];
            acc0[0] += q0*ev.x; acc0[1] += q0*ev.y;
            acc0[2] += q0*ev.z; acc0[3] += q0*ev.w;
            acc1[0] += q1*ev.x; acc1[1] += q1*ev.y;
            acc1[2] += q1*ev.z; acc1[3] += q1*ev.w;
        }
        #pragma unroll
        for (int j = 0; j < 4; j++) {
            if (rg + j < NRELV) {
                g_bias[ob + (size_t)r0*NRELV + rg + j]     = acc0[j];
                g_bias[ob + (size_t)(r0+1)*NRELV + rg + j] = acc1[j];
            }
        }
    }
}

// ---------------- fused attention ---------------------------------------------
__global__ void __launch_bounds__(256)
attn_kernel(const int* __restrict__ mask, const void* __restrict__ arc,
            const float* __restrict__ Ev)
{
    extern __shared__ float sm[];
    float* sS    = sm;               // 16*512
    float* sKV   = sm + 8192;        // 128*68
    float* sQ    = sKV + 8704;       // 16*64 (also ctx)
    float* sB    = sQ + 1024;        // 16*101
    float* sW    = sB + 1616;        // 16*101
    float* sZ    = sW + 1616;        // 16
    int*   sMask = (int*)(sZ + 16);  // 512

    const int qt = blockIdx.x, h = blockIdx.y, b = blockIdx.z;
    const int i0 = qt * 16;
    const int tid = threadIdx.x;
    const int is64 = g_arc_is64;
    const size_t bh     = (size_t)b*H_ + h;
    const size_t qbase  = (bh*S_ + i0)*HD_;
    const size_t kvbase = bh*S_*HD_;

    for (int i = tid; i < 16*HD_; i += 256) sQ[i] = g_q[qbase + i];
    for (int i = tid; i < 16*NRELV; i += 256) {
        sB[i] = g_bias[(bh*S_ + i0)*NRELV + i];
        sW[i] = 0.f;
    }
    for (int i = tid; i < S_; i += 256) sMask[i] = mask[b*S_ + i];
    __syncthreads();

    const int ig = tid >> 6;
    const int jl = tid & 63;
    for (int jt = 0; jt < 4; jt++) {
        const int j0 = jt * 128;
        for (int f = tid; f < 2048; f += 256) {
            int row = f >> 4, c = (f & 15) << 2;
            *(float4*)&sKV[row*68 + c] =
                *(const float4*)&g_k[kvbase + (size_t)(j0 + row)*HD_ + c];
        }
        __syncthreads();
        float acc0[4] = {0,0,0,0}, acc1[4] = {0,0,0,0};
        #pragma unroll
        for (int d = 0; d < 64; d += 4) {
            float4 k0 = *(const float4*)&sKV[jl*68 + d];
            float4 k1 = *(const float4*)&sKV[(jl + 64)*68 + d];
            #pragma unroll
            for (int r = 0; r < 4; r++) {
                float4 q = *(const float4*)&sQ[(ig*4 + r)*64 + d];
                acc0[r] += q.x*k0.x + q.y*k0.y + q.z*k0.z + q.w*k0.w;
                acc1[r] += q.x*k1.x + q.y*k1.y + q.z*k1.z + q.w*k1.w;
            }
        }
        #pragma unroll
        for (int r = 0; r < 4; r++) {
            sS[(ig*4 + r)*S_ + j0 + jl]      = acc0[r];
            sS[(ig*4 + r)*S_ + j0 + 64 + jl] = acc1[r];
        }
        __syncthreads();
    }

    const size_t arcbase = ((size_t)b*S_ + i0)*S_;
    for (int idx = tid; idx < 16*S_; idx += 256) {
        int i = idx >> 9, j = idx & (S_-1);
        int rel = arc_at(arc, is64, arcbase + (size_t)i*S_ + j);
        float s = (sS[idx] + sB[i*NRELV + rel]) * 0.125f;
        if (sMask[j] == 0) s = -1e30f;
        sS[idx] = s;
    }
    __syncthreads();

    const int wrp = tid >> 5, lane = tid & 31;
    #pragma unroll
    for (int rr = 0; rr < 2; rr++) {
        int row = wrp*2 + rr;
        float m = -3.4e38f;
        for (int j = lane; j < S_; j += 32) m = fmaxf(m, sS[row*S_ + j]);
        #pragma unroll
        for (int o = 16; o; o >>= 1) m = fmaxf(m, __shfl_xor_sync(0xffffffffu, m, o));
        float z = 0.f;
        for (int j = lane; j < S_; j += 32) {
            float p = __expf(sS[row*S_ + j] - m);
            sS[row*S_ + j] = p;
            z += p;
        }
        #pragma unroll
        for (int o = 16; o; o >>= 1) z += __shfl_xor_sync(0xffffffffu, z, o);
        if (lane == 0) sZ[row] = z;
    }
    __syncthreads();

    for (int idx = tid; idx < 16*S_; idx += 256) {
        int i = idx >> 9, j = idx & (S_-1);
        int rel = arc_at(arc, is64, arcbase + (size_t)i*S_ + j);
        atomicAdd(&sW[i*NRELV + rel], sS[idx]);
    }
    for (int i = tid; i < 1024; i += 256) sQ[i] = 0.f;
    __syncthreads();

    const int jq  = tid >> 6;
    const int t64 = tid & 63;
    const int rg  = (t64 >> 4) << 2;
    const int e0  = (t64 & 15) << 2;
    float acc[4][4];
    #pragma unroll
    for (int r = 0; r < 4; r++)
        #pragma unroll
        for (int c2 = 0; c2 < 4; c2++) acc[r][c2] = 0.f;

    for (int jt = 0; jt < 4; jt++) {
        for (int f = tid; f < 2048; f += 256) {
            int row = f >> 4, c = (f & 15) << 2;
            *(float4*)&sKV[row*68 + c] =
                *(const float4*)&g_v[kvbase + (size_t)(jt*128 + row)*HD_ + c];
        }
        __syncthreads();
        #pragma unroll 4
        for (int jj = 0; jj < 32; jj++) {
            int jlv = jq*32 + jj;
            int j   = jt*128 + jlv;
            float4 v = *(const float4*)&sKV[jlv*68 + e0];
            #pragma unroll
            for (int r = 0; r < 4; r++) {
                float p = sS[(rg + r)*S_ + j];
                acc[r][0] += p*v.x; acc[r][1] += p*v.y;
                acc[r][2] += p*v.z; acc[r][3] += p*v.w;
            }
        }
        __syncthreads();
    }
    #pragma unroll
    for (int r = 0; r < 4; r++) {
        atomicAdd(&sQ[(rg+r)*64 + e0 + 0], acc[r][0]);
        atomicAdd(&sQ[(rg+r)*64 + e0 + 1], acc[r][1]);
        atomicAdd(&sQ[(rg+r)*64 + e0 + 2], acc[r][2]);
        atomicAdd(&sQ[(rg+r)*64 + e0 + 3], acc[r][3]);
    }

    for (int i = tid; i < NRELV*HD_; i += 256) sKV[i] = Ev[i];
    __syncthreads();

    const int e  = tid & 63;
    const int r0 = (tid >> 6) * 4;
    float cv[4] = {0,0,0,0};
    for (int rel = 0; rel < NRELV; rel++) {
        float ev = sKV[rel*64 + e];
        #pragma unroll
        for (int r = 0; r < 4; r++) cv[r] += sW[(r0 + r)*NRELV + rel] * ev;
    }
    #pragma unroll
    for (int r = 0; r < 4; r++) {
        int row = r0 + r;
        float val = (sQ[row*64 + e] + cv[r]) / sZ[row];
        g_ctx[((size_t)b*S_ + i0 + row)*D_ + h*HD_ + e] = val;
    }
}

// ---------------- launch --------------------------------------------------------
extern "C" void kernel_launch(void* const* d_in, const int* in_sizes, int n_in,
                              void* d_out, int out_size)
{
    (void)in_sizes; (void)n_in; (void)out_size;
    const float* query = (const float*)d_in[0];
    const float* key_  = (const float*)d_in[1];
    const float* value = (const float*)d_in[2];
    const int*   mask  = (const int*)d_in[3];
    const void*  arc   = d_in[4];
    const float* Wq = (const float*)d_in[5];
    const float* bq = (const float*)d_in[6];
    const float* Wk = (const float*)d_in[7];
    const float* bk = (const float*)d_in[8];
    const float* Wv = (const float*)d_in[9];
    const float* bv = (const float*)d_in[10];
    const float* Wo = (const float*)d_in[11];
    const float* bo = (const float*)d_in[12];
    const float* Ek = (const float*)d_in[13];
    const float* Eq = (const float*)d_in[14];
    const float* Ev = (const float*)d_in[15];
    float* out = (float*)d_out;

    const size_t smem2 = (size_t)(128*104 + 32*128) * sizeof(float);
    const size_t smem3 = (size_t)(8192 + 8704 + 1024 + 1616 + 1616 + 16) * sizeof(float)
                       + 512 * sizeof(int);
    cudaFuncSetAttribute(bias_kernel, cudaFuncAttributeMaxDynamicSharedMemorySize, (int)smem2);
    cudaFuncSetAttribute(attn_kernel, cudaFuncAttributeMaxDynamicSharedMemorySize, (int)smem3);

    float *gq, *gk, *gv, *gctx;
    cudaGetSymbolAddress((void**)&gq,   g_q);
    cudaGetSymbolAddress((void**)&gk,   g_k);
    cudaGetSymbolAddress((void**)&gv,   g_v);
    cudaGetSymbolAddress((void**)&gctx, g_ctx);

    detect_kernel<<<1, 256>>>((const int*)arc);

    GemmArgs qkv;
    qkv.X[0] = query; qkv.X[1] = key_; qkv.X[2] = value;
    qkv.W[0] = Wq;    qkv.W[1] = Wk;   qkv.W[2] = Wv;
    qkv.b[0] = bq;    qkv.b[1] = bk;   qkv.b[2] = bv;
    qkv.o[0] = gq;    qkv.o[1] = gk;   qkv.o[2] = gv;

    GemmArgs oproj;
    oproj.X[0] = gctx; oproj.W[0] = Wo; oproj.b[0] = bo; oproj.o[0] = out;
    oproj.X[1] = oproj.X[2] = nullptr;
    oproj.W[1] = oproj.W[2] = nullptr;
    oproj.b[1] = oproj.b[2] = nullptr;
    oproj.o[1] = oproj.o[2] = nullptr;

    dim3 qkvGrid(D_/BN, (B_*S_)/BM, 3);   // (6, 16, 3)
    mma_gemm_kernel<0><<<qkvGrid, 256>>>(qkv);

    bias_kernel<<<dim3(S_/32, H_, B_), 256, smem2>>>(Ek, Eq);
    attn_kernel<<<dim3(S_/16, H_, B_), 256, smem3>>>(mask, arc, Ev);

    dim3 oGrid(D_/BN, (B_*S_)/BM, 1);     // (6, 16, 1)
    mma_gemm_kernel<1><<<oGrid, 256>>>(oproj);
}

// round 4
// speedup vs baseline: 2.5267x; 1.0618x over previous
#include <cuda_runtime.h>
#include <cuda_bf16.h>
#include <cstdint>
#include <cstddef>

#define B_    4
#define S_    512
#define D_    768
#define H_    12
#define HD_   64
#define NRELV 101
#define XN    (B_*S_*D_)   // 1572864
#define WN    (D_*D_)      // 589824

#define BM    128
#define BN    128
#define BK    32
#define LDSB  40           // bf16 stride (80B) -> ldmatrix conflict-free

// ---------------- scratch ------------------------------------------------------
__device__ float g_q[B_*H_*S_*HD_];
__device__ float g_k[B_*H_*S_*HD_];
__device__ __nv_bfloat16 g_khi[XN], g_klo[XN];
__device__ __nv_bfloat16 g_vhi[XN], g_vlo[XN];
__device__ __nv_bfloat16 g_xhi[3*XN], g_xlo[3*XN];
__device__ __nv_bfloat16 g_whi[4*WN], g_wlo[4*WN];
__device__ __nv_bfloat16 g_chi[XN], g_clo[XN];
__device__ float g_bias[(size_t)B_*H_*S_*NRELV];
__device__ int   g_arc_is64;

// ---------------- helpers ------------------------------------------------------
__device__ __forceinline__ void split2(float a, float b, uint32_t& hi, uint32_t& lo)
{
    __nv_bfloat16 h0 = __float2bfloat16(a);
    __nv_bfloat16 h1 = __float2bfloat16(b);
    __nv_bfloat16 l0 = __float2bfloat16(a - __bfloat162float(h0));
    __nv_bfloat16 l1 = __float2bfloat16(b - __bfloat162float(h1));
    hi = (uint32_t)*(unsigned short*)&h0 | ((uint32_t)*(unsigned short*)&h1 << 16);
    lo = (uint32_t)*(unsigned short*)&l0 | ((uint32_t)*(unsigned short*)&l1 << 16);
}

__device__ __forceinline__ void ldsm_x4(uint32_t addr, uint32_t& r0, uint32_t& r1,
                                        uint32_t& r2, uint32_t& r3)
{
    asm volatile("ldmatrix.sync.aligned.m8n8.x4.shared.b16 {%0,%1,%2,%3}, [%4];"
                 : "=r"(r0), "=r"(r1), "=r"(r2), "=r"(r3) : "r"(addr));
}

__device__ __forceinline__ void ldsm_x2_trans(uint32_t addr, uint32_t& r0, uint32_t& r1)
{
    asm volatile("ldmatrix.sync.aligned.m8n8.x2.trans.shared.b16 {%0,%1}, [%2];"
                 : "=r"(r0), "=r"(r1) : "r"(addr));
}

__device__ __forceinline__ void mma16816(float* c, const uint32_t* a,
                                         uint32_t b0, uint32_t b1)
{
    asm volatile(
        "mma.sync.aligned.m16n8k16.row.col.f32.bf16.bf16.f32 "
        "{%0,%1,%2,%3}, {%4,%5,%6,%7}, {%8,%9}, {%0,%1,%2,%3};"
        : "+f"(c[0]), "+f"(c[1]), "+f"(c[2]), "+f"(c[3])
        : "r"(a[0]), "r"(a[1]), "r"(a[2]), "r"(a[3]), "r"(b0), "r"(b1));
}

// ---------------- graph_arc dtype detection ------------------------------------
__global__ void detect_kernel(const int* __restrict__ arc32)
{
    __shared__ int cnt;
    if (threadIdx.x == 0) cnt = 0;
    __syncthreads();
    int local = 0;
    for (int i = threadIdx.x; i < 1024; i += blockDim.x)
        if (arc32[2*i + 1] != 0) local++;
    if (local) atomicAdd(&cnt, local);
    __syncthreads();
    if (threadIdx.x == 0) g_arc_is64 = (cnt == 0) ? 1 : 0;
}

__device__ __forceinline__ int arc_at(const void* arc, int is64, size_t idx)
{
    if (is64) return (int)(((const long long*)arc)[idx]);
    return ((const int*)arc)[idx];
}

// ---------------- prepass: fp32 -> bf16 hi/lo split -----------------------------
struct SplitArgs {
    const float*   src[7];
    __nv_bfloat16* hi[7];
    __nv_bfloat16* lo[7];
    int            n[7];
};

__global__ void __launch_bounds__(256)
split_kernel(SplitArgs a)
{
    const int w = blockIdx.y;
    const int n = a.n[w];
    const int i = (blockIdx.x * 256 + threadIdx.x) * 4;
    if (i >= n) return;
    float4 v = *(const float4*)(a.src[w] + i);
    uint32_t h0, l0, h1, l1;
    split2(v.x, v.y, h0, l0);
    split2(v.z, v.w, h1, l1);
    *(uint2*)(a.hi[w] + i) = make_uint2(h0, h1);
    *(uint2*)(a.lo[w] + i) = make_uint2(l0, l1);
}

// ---------------- tensor-core GEMM (pre-split bf16 inputs) ----------------------
template<int MODE>
__global__ void __launch_bounds__(256, 1)
mma_gemm_kernel(const float* __restrict__ bias0, const float* __restrict__ bias1,
                const float* __restrict__ bias2, float* __restrict__ out1)
{
    __shared__ __nv_bfloat16 sXhi[BM][LDSB], sXlo[BM][LDSB];
    __shared__ __nv_bfloat16 sWhi[BN][LDSB], sWlo[BN][LDSB];

    const int z = (MODE == 0) ? blockIdx.z : 0;
    const __nv_bfloat16 *Xhi, *Xlo, *Whi, *Wlo;
    const float* bias;
    if (MODE == 0) {
        Xhi = g_xhi + (size_t)z*XN;  Xlo = g_xlo + (size_t)z*XN;
        Whi = g_whi + (size_t)z*WN;  Wlo = g_wlo + (size_t)z*WN;
        bias = (z == 0) ? bias0 : (z == 1) ? bias1 : bias2;
    } else {
        Xhi = g_chi;  Xlo = g_clo;
        Whi = g_whi + (size_t)3*WN;  Wlo = g_wlo + (size_t)3*WN;
        bias = bias0;
    }

    const int tid  = threadIdx.x;
    const int lane = tid & 31;
    const int warp = tid >> 5;
    const int wm   = warp & 3;
    const int wn   = warp >> 2;
    const int m0   = blockIdx.y * BM;
    const int n0   = blockIdx.x * BN;

    float acc[2][8][4];
    #pragma unroll
    for (int mt = 0; mt < 2; mt++)
        #pragma unroll
        for (int nt = 0; nt < 8; nt++)
            #pragma unroll
            for (int j = 0; j < 4; j++) acc[mt][nt][j] = 0.f;

    const int mat = lane >> 3, mr = lane & 7;
    const int a_row = (mat & 1) * 8 + mr;
    const int a_k   = (mat >> 1) * 8;
    const uint32_t aHi = (uint32_t)__cvta_generic_to_shared(&sXhi[wm*32 + a_row][a_k]);
    const uint32_t aLo = (uint32_t)__cvta_generic_to_shared(&sXlo[wm*32 + a_row][a_k]);
    const int b_row = (mat >> 1) * 8 + mr;
    const int b_k   = (mat & 1) * 8;
    const uint32_t bHi = (uint32_t)__cvta_generic_to_shared(&sWhi[wn*64 + b_row][b_k]);
    const uint32_t bLo = (uint32_t)__cvta_generic_to_shared(&sWlo[wn*64 + b_row][b_k]);

    const int ldrow = tid >> 1;          // 0..127
    const int ldq   = (tid & 1) * 2;     // quad base (2 uint4 each)

    for (int k0 = 0; k0 < D_; k0 += BK) {
        uint4 xh[2], xl[2], wh[2], wl[2];
        #pragma unroll
        for (int u = 0; u < 2; u++) {
            const size_t xo = (size_t)(m0 + ldrow)*D_ + k0 + (ldq + u)*8;
            const size_t wo = (size_t)(n0 + ldrow)*D_ + k0 + (ldq + u)*8;
            xh[u] = *(const uint4*)(Xhi + xo);
            xl[u] = *(const uint4*)(Xlo + xo);
            wh[u] = *(const uint4*)(Whi + wo);
            wl[u] = *(const uint4*)(Wlo + wo);
        }
        __syncthreads();
        #pragma unroll
        for (int u = 0; u < 2; u++) {
            *(uint4*)&sXhi[ldrow][(ldq+u)*8] = xh[u];
            *(uint4*)&sXlo[ldrow][(ldq+u)*8] = xl[u];
            *(uint4*)&sWhi[ldrow][(ldq+u)*8] = wh[u];
            *(uint4*)&sWlo[ldrow][(ldq+u)*8] = wl[u];
        }
        __syncthreads();

        #pragma unroll
        for (int ks = 0; ks < 2; ks++) {
            const uint32_t ko = ks * 32;
            uint32_t ah[2][4], al[2][4];
            #pragma unroll
            for (int mt = 0; mt < 2; mt++) {
                const uint32_t mo = mt * (16 * LDSB * 2);
                ldsm_x4(aHi + mo + ko, ah[mt][0], ah[mt][1], ah[mt][2], ah[mt][3]);
                ldsm_x4(aLo + mo + ko, al[mt][0], al[mt][1], al[mt][2], al[mt][3]);
            }
            #pragma unroll
            for (int pr = 0; pr < 4; pr++) {
                const uint32_t po = pr * (16 * LDSB * 2);
                uint32_t bh[4], bl[4];
                ldsm_x4(bHi + po + ko, bh[0], bh[1], bh[2], bh[3]);
                ldsm_x4(bLo + po + ko, bl[0], bl[1], bl[2], bl[3]);
                #pragma unroll
                for (int h2 = 0; h2 < 2; h2++) {
                    const int nt = pr*2 + h2;
                    #pragma unroll
                    for (int mt = 0; mt < 2; mt++) {
                        mma16816(acc[mt][nt], ah[mt], bh[h2*2], bh[h2*2+1]);
                        mma16816(acc[mt][nt], ah[mt], bl[h2*2], bl[h2*2+1]);
                        mma16816(acc[mt][nt], al[mt], bh[h2*2], bh[h2*2+1]);
                    }
                }
            }
        }
    }

    // ---- epilogue ----
    const int gid = lane >> 2, tig = lane & 3;
    #pragma unroll
    for (int mt = 0; mt < 2; mt++) {
        const int rbase = m0 + wm*32 + mt*16 + gid;
        #pragma unroll
        for (int nt = 0; nt < 8; nt++) {
            const int col = n0 + wn*64 + nt*8 + tig*2;
            const float b0v = bias[col], b1v = bias[col+1];
            float v00 = acc[mt][nt][0] + b0v;
            float v01 = acc[mt][nt][1] + b1v;
            float v10 = acc[mt][nt][2] + b0v;
            float v11 = acc[mt][nt][3] + b1v;
            if (MODE == 0) {
                const int hh = col >> 6, e = col & 63;
                #pragma unroll
                for (int half = 0; half < 2; half++) {
                    const int r = rbase + half*8;
                    const int b = r >> 9, s = r & (S_-1);
                    const size_t o = (((size_t)(b*H_ + hh)*S_ + s) << 6) + e;
                    const float va = half ? v10 : v00;
                    const float vb = half ? v11 : v01;
                    if (z == 0) {
                        g_q[o] = va; g_q[o+1] = vb;
                    } else if (z == 1) {
                        g_k[o] = va; g_k[o+1] = vb;
                        uint32_t hi, lo; split2(va, vb, hi, lo);
                        *(uint32_t*)&g_khi[o] = hi;
                        *(uint32_t*)&g_klo[o] = lo;
                    } else {
                        uint32_t hi, lo; split2(va, vb, hi, lo);
                        *(uint32_t*)&g_vhi[o] = hi;
                        *(uint32_t*)&g_vlo[o] = lo;
                    }
                }
            } else {
                out1[(size_t)rbase*D_ + col]       = v00;
                out1[(size_t)rbase*D_ + col + 1]   = v01;
                out1[(size_t)(rbase+8)*D_ + col]   = v10;
                out1[(size_t)(rbase+8)*D_ + col+1] = v11;
            }
        }
    }
}

// ---------------- bias table: bias[b,h,s,rel] = q_s.Ek[rel] + k_s.Eq[rel] -------
__global__ void __launch_bounds__(256)
bias_kernel(const float* __restrict__ Ek, const float* __restrict__ Eq)
{
    extern __shared__ float sm[];
    float* sE  = sm;              // [128][104]
    float* sQK = sm + 128*104;    // [32][128]
    const int b  = blockIdx.z, h = blockIdx.y, s0 = blockIdx.x * 32;
    const int tid = threadIdx.x;

    for (int i = tid; i < NRELV*HD_; i += 256) {
        int rel = i >> 6, e = i & 63;
        sE[e*104 + rel]        = Ek[i];
        sE[(64 + e)*104 + rel] = Eq[i];
    }
    if (tid < 128) {
        sE[tid*104 + 101] = 0.f; sE[tid*104 + 102] = 0.f; sE[tid*104 + 103] = 0.f;
    }
    const size_t base = ((size_t)(b*H_ + h)*S_ + s0)*HD_;
    for (int i = tid; i < 32*64; i += 256) {
        int r = i >> 6, e = i & 63;
        sQK[r*128 + e]      = g_q[base + i];
        sQK[r*128 + 64 + e] = g_k[base + i];
    }
    __syncthreads();

    const size_t ob = ((size_t)(b*H_ + h)*S_ + s0)*NRELV;
    for (int c = tid; c < 16*26; c += 256) {
        int r0 = (c / 26) * 2;
        int rg = (c % 26) * 4;
        float acc0[4] = {0,0,0,0}, acc1[4] = {0,0,0,0};
        const float* q0p = &sQK[r0*128];
        const float* q1p = &sQK[(r0+1)*128];
        #pragma unroll 4
        for (int d = 0; d < 128; d++) {
            float q0 = q0p[d], q1 = q1p[d];
            float4 ev = *(const float4*)&sE[d*104 + rg];
            acc0[0] += q0*ev.x; acc0[1] += q0*ev.y;
            acc0[2] += q0*ev.z; acc0[3] += q0*ev.w;
            acc1[0] += q1*ev.x; acc1[1] += q1*ev.y;
            acc1[2] += q1*ev.z; acc1[3] += q1*ev.w;
        }
        #pragma unroll
        for (int j = 0; j < 4; j++) {
            if (rg + j < NRELV) {
                g_bias[ob + (size_t)r0*NRELV + rg + j]     = acc0[j];
                g_bias[ob + (size_t)(r0+1)*NRELV + rg + j] = acc1[j];
            }
        }
    }
}

// ---------------- fused attention (tensor-core QK & PV) -------------------------
#define SSTR 520
#define OFF_SS    0                       // 16*520*4 = 33280
#define OFF_KHI   33280                   // 128*72*2 = 18432
#define OFF_KLO   51712                   // -> 70144
#define OFF_EV    33280                   // Ev fp32 101*64 (reuses K region)
#define OFF_SQ    70144                   // 16*64*4 = 4096
#define OFF_SB    74240                   // 16*101*4 = 6464
#define OFF_SW    80704                   // 6464
#define OFF_SZ    87168                   // 64
#define OFF_MASK  87232                   // 2048
#define SMEM_ATTN 89280

__global__ void __launch_bounds__(256, 2)
attn_kernel(const int* __restrict__ mask, const void* __restrict__ arc,
            const float* __restrict__ Ev)
{
    extern __shared__ char smraw[];
    float* sS    = (float*)(smraw + OFF_SS);
    __nv_bfloat16* sKhi = (__nv_bfloat16*)(smraw + OFF_KHI);
    __nv_bfloat16* sKlo = (__nv_bfloat16*)(smraw + OFF_KLO);
    float* sEv   = (float*)(smraw + OFF_EV);
    float* sQ    = (float*)(smraw + OFF_SQ);
    float* sB    = (float*)(smraw + OFF_SB);
    float* sW    = (float*)(smraw + OFF_SW);
    float* sZ    = (float*)(smraw + OFF_SZ);
    int*   sMask = (int*)  (smraw + OFF_MASK);

    const int qt = blockIdx.x, h = blockIdx.y, b = blockIdx.z;
    const int i0 = qt * 16;
    const int tid  = threadIdx.x;
    const int lane = tid & 31;
    const int warp = tid >> 5;
    const int is64 = g_arc_is64;
    const size_t bh     = (size_t)b*H_ + h;
    const size_t qbase  = (bh*S_ + i0)*HD_;
    const size_t kvbase = bh*S_*HD_;

    for (int i = tid; i < 16*HD_; i += 256) sQ[i] = g_q[qbase + i];
    for (int i = tid; i < 16*NRELV; i += 256) {
        sB[i] = g_bias[(bh*S_ + i0)*NRELV + i];
        sW[i] = 0.f;
    }
    for (int i = tid; i < S_; i += 256) sMask[i] = mask[b*S_ + i];
    __syncthreads();

    // ---- Q A-fragments (bf16 hi/lo) ----
    uint32_t qah[4][4], qal[4][4];
    {
        const int qr = lane >> 2;
        const int qc = (lane & 3) * 2;
        #pragma unroll
        for (int kk = 0; kk < 4; kk++) {
            float2 x0 = *(float2*)&sQ[qr*64     + kk*16 + qc];
            float2 x1 = *(float2*)&sQ[(qr+8)*64 + kk*16 + qc];
            float2 x2 = *(float2*)&sQ[qr*64     + kk*16 + qc + 8];
            float2 x3 = *(float2*)&sQ[(qr+8)*64 + kk*16 + qc + 8];
            split2(x0.x, x0.y, qah[kk][0], qal[kk][0]);
            split2(x1.x, x1.y, qah[kk][1], qal[kk][1]);
            split2(x2.x, x2.y, qah[kk][2], qal[kk][2]);
            split2(x3.x, x3.y, qah[kk][3], qal[kk][3]);
        }
    }

    // tile copy mapping: 2 threads/row, each copies a contiguous 32-elem half
    const int copyrow  = tid >> 1;           // 0..127
    const int chalf    = (tid & 1) * 32;     // element offset 0 or 32

    // ---- pass 1: S = Q K^T via mma ----
    for (int jt = 0; jt < 4; jt++) {
        const int j0 = jt * 128;
        {
            const size_t src = kvbase + (size_t)(j0 + copyrow)*HD_ + chalf;
            #pragma unroll
            for (int u = 0; u < 4; u++) {
                *(uint4*)&sKhi[copyrow*72 + chalf + u*8] = *(const uint4*)(g_khi + src + u*8);
                *(uint4*)&sKlo[copyrow*72 + chalf + u*8] = *(const uint4*)(g_klo + src + u*8);
            }
        }
        __syncthreads();

        float c[2][4] = {{0,0,0,0},{0,0,0,0}};
        const int nw = warp * 16;
        #pragma unroll
        for (int kk = 0; kk < 4; kk++) {
            #pragma unroll
            for (int nt = 0; nt < 2; nt++) {
                const int j = nw + nt*8 + (lane >> 2);
                const int d = kk*16 + (lane & 3)*2;
                uint32_t bh0 = *(uint32_t*)&sKhi[j*72 + d];
                uint32_t bh1 = *(uint32_t*)&sKhi[j*72 + d + 8];
                uint32_t bl0 = *(uint32_t*)&sKlo[j*72 + d];
                uint32_t bl1 = *(uint32_t*)&sKlo[j*72 + d + 8];
                mma16816(c[nt], qah[kk], bh0, bh1);
                mma16816(c[nt], qah[kk], bl0, bl1);
                mma16816(c[nt], qal[kk], bh0, bh1);
            }
        }
        #pragma unroll
        for (int nt = 0; nt < 2; nt++) {
            const int col = j0 + nw + nt*8 + 2*(lane & 3);
            const int r   = lane >> 2;
            *(float2*)&sS[r*SSTR + col]     = make_float2(c[nt][0], c[nt][1]);
            *(float2*)&sS[(r+8)*SSTR + col] = make_float2(c[nt][2], c[nt][3]);
        }
        __syncthreads();
    }

    // ---- relation bias + scale + mask ----
    const size_t arcbase = ((size_t)b*S_ + i0)*S_;
    for (int idx = tid; idx < 16*S_; idx += 256) {
        int i = idx >> 9, j = idx & (S_-1);
        int rel = arc_at(arc, is64, arcbase + (size_t)i*S_ + j);
        float s = (sS[i*SSTR + j] + sB[i*NRELV + rel]) * 0.125f;
        if (sMask[j] == 0) s = -1e30f;
        sS[i*SSTR + j] = s;
    }
    __syncthreads();

    // ---- softmax ----
    #pragma unroll
    for (int rr = 0; rr < 2; rr++) {
        int row = warp*2 + rr;
        float m = -3.4e38f;
        for (int j = lane; j < S_; j += 32) m = fmaxf(m, sS[row*SSTR + j]);
        #pragma unroll
        for (int o = 16; o; o >>= 1) m = fmaxf(m, __shfl_xor_sync(0xffffffffu, m, o));
        float z = 0.f;
        for (int j = lane; j < S_; j += 32) {
            float p = __expf(sS[row*SSTR + j] - m);
            sS[row*SSTR + j] = p;
            z += p;
        }
        #pragma unroll
        for (int o = 16; o; o >>= 1) z += __shfl_xor_sync(0xffffffffu, z, o);
        if (lane == 0) sZ[row] = z;
    }
    __syncthreads();

    // ---- relation binning ----
    for (int idx = tid; idx < 16*S_; idx += 256) {
        int i = idx >> 9, j = idx & (S_-1);
        int rel = arc_at(arc, is64, arcbase + (size_t)i*S_ + j);
        atomicAdd(&sW[i*NRELV + rel], sS[i*SSTR + j]);
    }
    __syncthreads();

    // ---- pass 2: ctx = P V via mma ----
    float c2[8][4];
    #pragma unroll
    for (int nt = 0; nt < 8; nt++)
        #pragma unroll
        for (int j = 0; j < 4; j++) c2[nt][j] = 0.f;

    const uint32_t vhiBase = (uint32_t)__cvta_generic_to_shared(sKhi);
    const uint32_t vloBase = (uint32_t)__cvta_generic_to_shared(sKlo);
    for (int jt = 0; jt < 4; jt++) {
        {
            const size_t src = kvbase + (size_t)(jt*128 + copyrow)*HD_ + chalf;
            #pragma unroll
            for (int u = 0; u < 4; u++) {
                *(uint4*)&sKhi[copyrow*72 + chalf + u*8] = *(const uint4*)(g_vhi + src + u*8);
                *(uint4*)&sKlo[copyrow*72 + chalf + u*8] = *(const uint4*)(g_vlo + src + u*8);
            }
        }
        __syncthreads();

        const int jb = jt*128 + warp*16;
        uint32_t pah[4], pal[4];
        {
            const int pr = lane >> 2;
            const int pc = (lane & 3) * 2;
            float2 x0 = *(float2*)&sS[pr*SSTR     + jb + pc];
            float2 x1 = *(float2*)&sS[(pr+8)*SSTR + jb + pc];
            float2 x2 = *(float2*)&sS[pr*SSTR     + jb + pc + 8];
            float2 x3 = *(float2*)&sS[(pr+8)*SSTR + jb + pc + 8];
            split2(x0.x, x0.y, pah[0], pal[0]);
            split2(x1.x, x1.y, pah[1], pal[1]);
            split2(x2.x, x2.y, pah[2], pal[2]);
            split2(x3.x, x3.y, pah[3], pal[3]);
        }
        const uint32_t rowoff = (uint32_t)(warp*16 + (lane & 15)) * 144;
        #pragma unroll
        for (int nt = 0; nt < 8; nt++) {
            uint32_t bh0, bh1, bl0, bl1;
            ldsm_x2_trans(vhiBase + rowoff + nt*16, bh0, bh1);
            ldsm_x2_trans(vloBase + rowoff + nt*16, bl0, bl1);
            mma16816(c2[nt], pah, bh0, bh1);
            mma16816(c2[nt], pah, bl0, bl1);
            mma16816(c2[nt], pal, bh0, bh1);
        }
        __syncthreads();
    }

    // ---- cross-warp reduction of PV partials (reuse sS) + load Ev ----
    {
        float* red = sS;
        const int r = lane >> 2;
        #pragma unroll
        for (int nt = 0; nt < 8; nt++) {
            const int col = nt*8 + 2*(lane & 3);
            red[warp*1024 + r*64 + col]       = c2[nt][0];
            red[warp*1024 + r*64 + col + 1]   = c2[nt][1];
            red[warp*1024 + (r+8)*64 + col]   = c2[nt][2];
            red[warp*1024 + (r+8)*64 + col+1] = c2[nt][3];
        }
    }
    for (int i = tid; i < NRELV*HD_; i += 256) sEv[i] = Ev[i];
    __syncthreads();

    // ---- final: reduce, + wrel@Ev, /Z, store ctx as bf16 hi/lo ----
    {
        const int row = tid >> 4;            // 0..15
        const int e0  = (tid & 15) * 4;      // 0..60
        float4 acc = make_float4(0,0,0,0);
        #pragma unroll
        for (int w = 0; w < 8; w++) {
            float4 p = *(float4*)&sS[w*1024 + row*64 + e0];
            acc.x += p.x; acc.y += p.y; acc.z += p.z; acc.w += p.w;
        }
        const float* wrow = &sW[row*NRELV];
        for (int rel = 0; rel < NRELV; rel++) {
            float wv = wrow[rel];
            float4 ev = *(float4*)&sEv[rel*64 + e0];
            acc.x += wv*ev.x; acc.y += wv*ev.y; acc.z += wv*ev.z; acc.w += wv*ev.w;
        }
        const float rz = 1.f / sZ[row];
        acc.x *= rz; acc.y *= rz; acc.z *= rz; acc.w *= rz;

        uint32_t h0, l0, h1, l1;
        split2(acc.x, acc.y, h0, l0);
        split2(acc.z, acc.w, h1, l1);
        const size_t o = ((size_t)(b*S_ + i0 + row))*D_ + h*HD_ + e0;
        *(uint2*)&g_chi[o] = make_uint2(h0, h1);
        *(uint2*)&g_clo[o] = make_uint2(l0, l1);
    }
}

// ---------------- launch --------------------------------------------------------
extern "C" void kernel_launch(void* const* d_in, const int* in_sizes, int n_in,
                              void* d_out, int out_size)
{
    (void)in_sizes; (void)n_in; (void)out_size;
    const float* query = (const float*)d_in[0];
    const float* key_  = (const float*)d_in[1];
    const float* value = (const float*)d_in[2];
    const int*   mask  = (const int*)d_in[3];
    const void*  arc   = d_in[4];
    const float* bq = (const float*)d_in[6];
    const float* bk = (const float*)d_in[8];
    const float* bv = (const float*)d_in[10];
    const float* bo = (const float*)d_in[12];
    const float* Ek = (const float*)d_in[13];
    const float* Eq = (const float*)d_in[14];
    const float* Ev = (const float*)d_in[15];
    float* out = (float*)d_out;

    const size_t smem2 = (size_t)(128*104 + 32*128) * sizeof(float);
    cudaFuncSetAttribute(bias_kernel, cudaFuncAttributeMaxDynamicSharedMemorySize, (int)smem2);
    cudaFuncSetAttribute(attn_kernel, cudaFuncAttributeMaxDynamicSharedMemorySize, SMEM_ATTN);

    __nv_bfloat16 *xhi, *xlo, *whi, *wlo;
    cudaGetSymbolAddress((void**)&xhi, g_xhi);
    cudaGetSymbolAddress((void**)&xlo, g_xlo);
    cudaGetSymbolAddress((void**)&whi, g_whi);
    cudaGetSymbolAddress((void**)&wlo, g_wlo);

    detect_kernel<<<1, 256>>>((const int*)arc);

    SplitArgs sa;
    const float* srcs[7] = {query, key_, value,
                            (const float*)d_in[5], (const float*)d_in[7],
                            (const float*)d_in[9], (const float*)d_in[11]};
    for (int i = 0; i < 7; i++) {
        sa.src[i] = srcs[i];
        if (i < 3) {
            sa.hi[i] = xhi + (size_t)i*XN;
            sa.lo[i] = xlo + (size_t)i*XN;
            sa.n[i]  = XN;
        } else {
            sa.hi[i] = whi + (size_t)(i-3)*WN;
            sa.lo[i] = wlo + (size_t)(i-3)*WN;
            sa.n[i]  = WN;
        }
    }
    split_kernel<<<dim3((XN/4 + 255)/256, 7), 256>>>(sa);

    dim3 qkvGrid(D_/BN, (B_*S_)/BM, 3);
    mma_gemm_kernel<0><<<qkvGrid, 256>>>(bq, bk, bv, nullptr);

    bias_kernel<<<dim3(S_/32, H_, B_), 256, smem2>>>(Ek, Eq);
    attn_kernel<<<dim3(S_/16, H_, B_), 256, SMEM_ATTN>>>(mask, arc, Ev);

    dim3 oGrid(D_/BN, (B_*S_)/BM, 1);
    mma_gemm_kernel<1><<<oGrid, 256>>>(bo, nullptr, nullptr, out);
}

// round 5
// speedup vs baseline: 2.8507x; 1.1282x over previous
#include <cuda_runtime.h>
#include <cuda_bf16.h>
#include <cstdint>
#include <cstddef>

#define B_    4
#define S_    512
#define D_    768
#define H_    12
#define HD_   64
#define NRELV 101
#define EROWS 112          // NRELV padded to 14 n8-tiles
#define XN    (B_*S_*D_)   // 1572864
#define WN    (D_*D_)      // 589824

#define BM    128
#define BN    128
#define BK    32
#define LDSB  40           // bf16 stride (80B) -> ldmatrix conflict-free

// ---------------- scratch ------------------------------------------------------
__device__ __nv_bfloat16 g_qkhi[(size_t)B_*H_*S_*128], g_qklo[(size_t)B_*H_*S_*128];
__device__ __nv_bfloat16 g_vhi[XN], g_vlo[XN];
__device__ __nv_bfloat16 g_xhi[3*XN], g_xlo[3*XN];
__device__ __nv_bfloat16 g_whi[4*WN], g_wlo[4*WN];
__device__ __nv_bfloat16 g_chi[XN], g_clo[XN];
__device__ __nv_bfloat16 g_ehi[EROWS*128], g_elo[EROWS*128];
__device__ float g_bias[(size_t)B_*H_*S_*NRELV];
__device__ int   g_arc_is64;

// ---------------- helpers ------------------------------------------------------
__device__ __forceinline__ void split2(float a, float b, uint32_t& hi, uint32_t& lo)
{
    __nv_bfloat16 h0 = __float2bfloat16(a);
    __nv_bfloat16 h1 = __float2bfloat16(b);
    __nv_bfloat16 l0 = __float2bfloat16(a - __bfloat162float(h0));
    __nv_bfloat16 l1 = __float2bfloat16(b - __bfloat162float(h1));
    hi = (uint32_t)*(unsigned short*)&h0 | ((uint32_t)*(unsigned short*)&h1 << 16);
    lo = (uint32_t)*(unsigned short*)&l0 | ((uint32_t)*(unsigned short*)&l1 << 16);
}

__device__ __forceinline__ void ldsm_x4(uint32_t addr, uint32_t& r0, uint32_t& r1,
                                        uint32_t& r2, uint32_t& r3)
{
    asm volatile("ldmatrix.sync.aligned.m8n8.x4.shared.b16 {%0,%1,%2,%3}, [%4];"
                 : "=r"(r0), "=r"(r1), "=r"(r2), "=r"(r3) : "r"(addr));
}

__device__ __forceinline__ void ldsm_x2_trans(uint32_t addr, uint32_t& r0, uint32_t& r1)
{
    asm volatile("ldmatrix.sync.aligned.m8n8.x2.trans.shared.b16 {%0,%1}, [%2];"
                 : "=r"(r0), "=r"(r1) : "r"(addr));
}

__device__ __forceinline__ void mma16816(float* c, const uint32_t* a,
                                         uint32_t b0, uint32_t b1)
{
    asm volatile(
        "mma.sync.aligned.m16n8k16.row.col.f32.bf16.bf16.f32 "
        "{%0,%1,%2,%3}, {%4,%5,%6,%7}, {%8,%9}, {%0,%1,%2,%3};"
        : "+f"(c[0]), "+f"(c[1]), "+f"(c[2]), "+f"(c[3])
        : "r"(a[0]), "r"(a[1]), "r"(a[2]), "r"(a[3]), "r"(b0), "r"(b1));
}

// ---------------- graph_arc dtype detection ------------------------------------
__global__ void detect_kernel(const int* __restrict__ arc32)
{
    __shared__ int cnt;
    if (threadIdx.x == 0) cnt = 0;
    __syncthreads();
    int local = 0;
    for (int i = threadIdx.x; i < 1024; i += blockDim.x)
        if (arc32[2*i + 1] != 0) local++;
    if (local) atomicAdd(&cnt, local);
    __syncthreads();
    if (threadIdx.x == 0) g_arc_is64 = (cnt == 0) ? 1 : 0;
}

__device__ __forceinline__ int arc_at(const void* arc, int is64, size_t idx)
{
    if (is64) return (int)(((const long long*)arc)[idx]);
    return ((const int*)arc)[idx];
}

// ---------------- prepass: fp32 -> bf16 hi/lo split -----------------------------
struct SplitArgs {
    const float*   src[7];
    __nv_bfloat16* hi[7];
    __nv_bfloat16* lo[7];
    int            n[7];
};

__global__ void __launch_bounds__(256)
split_kernel(SplitArgs a)
{
    const int w = blockIdx.y;
    const int n = a.n[w];
    const int i = (blockIdx.x * 256 + threadIdx.x) * 4;
    if (i >= n) return;
    float4 v = *(const float4*)(a.src[w] + i);
    uint32_t h0, l0, h1, l1;
    split2(v.x, v.y, h0, l0);
    split2(v.z, v.w, h1, l1);
    *(uint2*)(a.hi[w] + i) = make_uint2(h0, h1);
    *(uint2*)(a.lo[w] + i) = make_uint2(l0, l1);
}

// E = [Ek | Eq] padded to 112x128, split to bf16 hi/lo
__global__ void __launch_bounds__(256)
ebuild_kernel(const float* __restrict__ Ek, const float* __restrict__ Eq)
{
    int idx = blockIdx.x * 256 + threadIdx.x;
    if (idx >= EROWS*128) return;
    int row = idx >> 7, col = idx & 127;
    float v = 0.f;
    if (row < NRELV) v = (col < 64) ? Ek[row*64 + col] : Eq[row*64 + col - 64];
    __nv_bfloat16 hv = __float2bfloat16(v);
    __nv_bfloat16 lv = __float2bfloat16(v - __bfloat162float(hv));
    g_ehi[idx] = hv;
    g_elo[idx] = lv;
}

// ---------------- tensor-core GEMM (pre-split bf16 inputs) ----------------------
// MODE 0: QKV (z=blockIdx.z). z0 -> g_qk cols 0-63; z1 -> g_qk cols 64-127;
//         z2 -> g_vhi/lo. MODE 1: ctx(hi/lo) @ Wo -> fp32 out (row-major).
template<int MODE>
__global__ void __launch_bounds__(256, 1)
mma_gemm_kernel(const float* __restrict__ bias0, const float* __restrict__ bias1,
                const float* __restrict__ bias2, float* __restrict__ out1)
{
    __shared__ __nv_bfloat16 sXhi[BM][LDSB], sXlo[BM][LDSB];
    __shared__ __nv_bfloat16 sWhi[BN][LDSB], sWlo[BN][LDSB];

    const int z = (MODE == 0) ? blockIdx.z : 0;
    const __nv_bfloat16 *Xhi, *Xlo, *Whi, *Wlo;
    const float* bias;
    if (MODE == 0) {
        Xhi = g_xhi + (size_t)z*XN;  Xlo = g_xlo + (size_t)z*XN;
        Whi = g_whi + (size_t)z*WN;  Wlo = g_wlo + (size_t)z*WN;
        bias = (z == 0) ? bias0 : (z == 1) ? bias1 : bias2;
    } else {
        Xhi = g_chi;  Xlo = g_clo;
        Whi = g_whi + (size_t)3*WN;  Wlo = g_wlo + (size_t)3*WN;
        bias = bias0;
    }

    const int tid  = threadIdx.x;
    const int lane = tid & 31;
    const int warp = tid >> 5;
    const int wm   = warp & 3;
    const int wn   = warp >> 2;
    const int m0   = blockIdx.y * BM;
    const int n0   = blockIdx.x * BN;

    float acc[2][8][4];
    #pragma unroll
    for (int mt = 0; mt < 2; mt++)
        #pragma unroll
        for (int nt = 0; nt < 8; nt++)
            #pragma unroll
            for (int j = 0; j < 4; j++) acc[mt][nt][j] = 0.f;

    const int mat = lane >> 3, mr = lane & 7;
    const int a_row = (mat & 1) * 8 + mr;
    const int a_k   = (mat >> 1) * 8;
    const uint32_t aHi = (uint32_t)__cvta_generic_to_shared(&sXhi[wm*32 + a_row][a_k]);
    const uint32_t aLo = (uint32_t)__cvta_generic_to_shared(&sXlo[wm*32 + a_row][a_k]);
    const int b_row = (mat >> 1) * 8 + mr;
    const int b_k   = (mat & 1) * 8;
    const uint32_t bHi = (uint32_t)__cvta_generic_to_shared(&sWhi[wn*64 + b_row][b_k]);
    const uint32_t bLo = (uint32_t)__cvta_generic_to_shared(&sWlo[wn*64 + b_row][b_k]);

    const int ldrow = tid >> 1;          // 0..127
    const int ldq   = (tid & 1) * 2;     // quad base (2 uint4 each)

    for (int k0 = 0; k0 < D_; k0 += BK) {
        uint4 xh[2], xl[2], wh[2], wl[2];
        #pragma unroll
        for (int u = 0; u < 2; u++) {
            const size_t xo = (size_t)(m0 + ldrow)*D_ + k0 + (ldq + u)*8;
            const size_t wo = (size_t)(n0 + ldrow)*D_ + k0 + (ldq + u)*8;
            xh[u] = *(const uint4*)(Xhi + xo);
            xl[u] = *(const uint4*)(Xlo + xo);
            wh[u] = *(const uint4*)(Whi + wo);
            wl[u] = *(const uint4*)(Wlo + wo);
        }
        __syncthreads();
        #pragma unroll
        for (int u = 0; u < 2; u++) {
            *(uint4*)&sXhi[ldrow][(ldq+u)*8] = xh[u];
            *(uint4*)&sXlo[ldrow][(ldq+u)*8] = xl[u];
            *(uint4*)&sWhi[ldrow][(ldq+u)*8] = wh[u];
            *(uint4*)&sWlo[ldrow][(ldq+u)*8] = wl[u];
        }
        __syncthreads();

        #pragma unroll
        for (int ks = 0; ks < 2; ks++) {
            const uint32_t ko = ks * 32;
            uint32_t ah[2][4], al[2][4];
            #pragma unroll
            for (int mt = 0; mt < 2; mt++) {
                const uint32_t mo = mt * (16 * LDSB * 2);
                ldsm_x4(aHi + mo + ko, ah[mt][0], ah[mt][1], ah[mt][2], ah[mt][3]);
                ldsm_x4(aLo + mo + ko, al[mt][0], al[mt][1], al[mt][2], al[mt][3]);
            }
            #pragma unroll
            for (int pr = 0; pr < 4; pr++) {
                const uint32_t po = pr * (16 * LDSB * 2);
                uint32_t bh[4], bl[4];
                ldsm_x4(bHi + po + ko, bh[0], bh[1], bh[2], bh[3]);
                ldsm_x4(bLo + po + ko, bl[0], bl[1], bl[2], bl[3]);
                #pragma unroll
                for (int h2 = 0; h2 < 2; h2++) {
                    const int nt = pr*2 + h2;
                    #pragma unroll
                    for (int mt = 0; mt < 2; mt++) {
                        mma16816(acc[mt][nt], ah[mt], bh[h2*2], bh[h2*2+1]);
                        mma16816(acc[mt][nt], ah[mt], bl[h2*2], bl[h2*2+1]);
                        mma16816(acc[mt][nt], al[mt], bh[h2*2], bh[h2*2+1]);
                    }
                }
            }
        }
    }

    // ---- epilogue ----
    const int gid = lane >> 2, tig = lane & 3;
    #pragma unroll
    for (int mt = 0; mt < 2; mt++) {
        const int rbase = m0 + wm*32 + mt*16 + gid;
        #pragma unroll
        for (int nt = 0; nt < 8; nt++) {
            const int col = n0 + wn*64 + nt*8 + tig*2;
            const float b0v = bias[col], b1v = bias[col+1];
            float v00 = acc[mt][nt][0] + b0v;
            float v01 = acc[mt][nt][1] + b1v;
            float v10 = acc[mt][nt][2] + b0v;
            float v11 = acc[mt][nt][3] + b1v;
            if (MODE == 0) {
                const int hh = col >> 6, e = col & 63;
                #pragma unroll
                for (int half = 0; half < 2; half++) {
                    const int r = rbase + half*8;
                    const int b = r >> 9, s = r & (S_-1);
                    const size_t rowb = (size_t)(b*H_ + hh)*S_ + s;
                    const float va = half ? v10 : v00;
                    const float vb = half ? v11 : v01;
                    uint32_t hi, lo; split2(va, vb, hi, lo);
                    if (z == 0) {
                        *(uint32_t*)&g_qkhi[rowb*128 + e] = hi;
                        *(uint32_t*)&g_qklo[rowb*128 + e] = lo;
                    } else if (z == 1) {
                        *(uint32_t*)&g_qkhi[rowb*128 + 64 + e] = hi;
                        *(uint32_t*)&g_qklo[rowb*128 + 64 + e] = lo;
                    } else {
                        *(uint32_t*)&g_vhi[rowb*64 + e] = hi;
                        *(uint32_t*)&g_vlo[rowb*64 + e] = lo;
                    }
                }
            } else {
                out1[(size_t)rbase*D_ + col]       = v00;
                out1[(size_t)rbase*D_ + col + 1]   = v01;
                out1[(size_t)(rbase+8)*D_ + col]   = v10;
                out1[(size_t)(rbase+8)*D_ + col+1] = v11;
            }
        }
    }
}

// ---------------- bias table via tensor cores -----------------------------------
// bias[bh, s, rel] = [q|k](s,:) . [Ek|Eq](rel,:)   -- A 128x128, B 112x128 per CTA
__global__ void __launch_bounds__(256, 1)
bias_mma_kernel()
{
    __shared__ __nv_bfloat16 sAhi[128][LDSB], sAlo[128][LDSB];
    __shared__ __nv_bfloat16 sBhi[EROWS][LDSB], sBlo[EROWS][LDSB];

    const int rt = blockIdx.x;           // 0..3 (128-row tile)
    const int h  = blockIdx.y, b = blockIdx.z;
    const size_t bh = (size_t)b*H_ + h;
    const size_t abase = (bh*S_ + rt*128) * 128;

    const int tid  = threadIdx.x;
    const int lane = tid & 31;
    const int warp = tid >> 5;           // 8 warps, 16 rows each

    float acc[14][4];
    #pragma unroll
    for (int nt = 0; nt < 14; nt++)
        #pragma unroll
        for (int j = 0; j < 4; j++) acc[nt][j] = 0.f;

    const int mat = lane >> 3, mr = lane & 7;
    const int a_row = (mat & 1) * 8 + mr;
    const int a_k   = (mat >> 1) * 8;
    const uint32_t aHi = (uint32_t)__cvta_generic_to_shared(&sAhi[warp*16 + a_row][a_k]);
    const uint32_t aLo = (uint32_t)__cvta_generic_to_shared(&sAlo[warp*16 + a_row][a_k]);
    const int b_row = (mat >> 1) * 8 + mr;
    const int b_k   = (mat & 1) * 8;
    const uint32_t bHi = (uint32_t)__cvta_generic_to_shared(&sBhi[b_row][b_k]);
    const uint32_t bLo = (uint32_t)__cvta_generic_to_shared(&sBlo[b_row][b_k]);

    for (int k0 = 0; k0 < 128; k0 += BK) {
        // A: 128 rows x 32 cols; 2 threads/row, 16 cols each
        {
            const int arow = tid >> 1;
            const int acol = (tid & 1) * 16;
            const size_t src = abase + (size_t)arow*128 + k0 + acol;
            uint4 h0 = *(const uint4*)(g_qkhi + src);
            uint4 h1 = *(const uint4*)(g_qkhi + src + 8);
            uint4 l0 = *(const uint4*)(g_qklo + src);
            uint4 l1 = *(const uint4*)(g_qklo + src + 8);
            __syncthreads();
            *(uint4*)&sAhi[arow][acol]     = h0;
            *(uint4*)&sAhi[arow][acol + 8] = h1;
            *(uint4*)&sAlo[arow][acol]     = l0;
            *(uint4*)&sAlo[arow][acol + 8] = l1;
        }
        // B: 112 rows x 32 cols; 224 thread-slots
        if (tid < EROWS*2) {
            const int brow = tid >> 1;
            const int bcol = (tid & 1) * 16;
            const size_t src = (size_t)brow*128 + k0 + bcol;
            *(uint4*)&sBhi[brow][bcol]     = *(const uint4*)(g_ehi + src);
            *(uint4*)&sBhi[brow][bcol + 8] = *(const uint4*)(g_ehi + src + 8);
            *(uint4*)&sBlo[brow][bcol]     = *(const uint4*)(g_elo + src);
            *(uint4*)&sBlo[brow][bcol + 8] = *(const uint4*)(g_elo + src + 8);
        }
        __syncthreads();

        #pragma unroll
        for (int ks = 0; ks < 2; ks++) {
            const uint32_t ko = ks * 32;
            uint32_t ah[4], al[4];
            ldsm_x4(aHi + ko, ah[0], ah[1], ah[2], ah[3]);
            ldsm_x4(aLo + ko, al[0], al[1], al[2], al[3]);
            #pragma unroll
            for (int pr = 0; pr < 7; pr++) {
                const uint32_t po = pr * (16 * LDSB * 2);
                uint32_t bhf[4], blf[4];
                ldsm_x4(bHi + po + ko, bhf[0], bhf[1], bhf[2], bhf[3]);
                ldsm_x4(bLo + po + ko, blf[0], blf[1], blf[2], blf[3]);
                #pragma unroll
                for (int h2 = 0; h2 < 2; h2++) {
                    const int nt = pr*2 + h2;
                    mma16816(acc[nt], ah, bhf[h2*2], bhf[h2*2+1]);
                    mma16816(acc[nt], ah, blf[h2*2], blf[h2*2+1]);
                    mma16816(acc[nt], al, bhf[h2*2], bhf[h2*2+1]);
                }
            }
        }
        __syncthreads();
    }

    // ---- epilogue: write bias (cols < 101) ----
    const int gid = lane >> 2, tig = lane & 3;
    const int row0 = rt*128 + warp*16 + gid;
    #pragma unroll
    for (int nt = 0; nt < 14; nt++) {
        const int col = nt*8 + tig*2;
        #pragma unroll
        for (int half = 0; half < 2; half++) {
            const int row = row0 + half*8;
            const size_t o = (bh*S_ + row)*NRELV;
            const float v0 = acc[nt][half*2];
            const float v1 = acc[nt][half*2+1];
            if (col < NRELV)     g_bias[o + col]     = v0;
            if (col + 1 < NRELV) g_bias[o + col + 1] = v1;
        }
    }
}

// ---------------- fused attention (tensor-core QK & PV) -------------------------
#define SSTR 520
#define OFF_SS    0                       // 16*520*4 = 33280
#define OFF_KHI   33280                   // 128*72*2 = 18432
#define OFF_KLO   51712                   // -> 70144
#define OFF_EV    33280                   // Ev fp32 101*64 (reuses K region)
#define OFF_SB    70144                   // 16*101*4 = 6464
#define OFF_SW    76608                   // 6464
#define OFF_SZ    83072                   // 64
#define OFF_MASK  83136                   // 2048
#define OFF_REL   85184                   // 16*512 u8 = 8192
#define SMEM_ATTN 93376

__global__ void __launch_bounds__(256, 2)
attn_kernel(const int* __restrict__ mask, const void* __restrict__ arc,
            const float* __restrict__ Ev)
{
    extern __shared__ char smraw[];
    float* sS    = (float*)(smraw + OFF_SS);
    __nv_bfloat16* sKhi = (__nv_bfloat16*)(smraw + OFF_KHI);
    __nv_bfloat16* sKlo = (__nv_bfloat16*)(smraw + OFF_KLO);
    float* sEv   = (float*)(smraw + OFF_EV);
    float* sB    = (float*)(smraw + OFF_SB);
    float* sW    = (float*)(smraw + OFF_SW);
    float* sZ    = (float*)(smraw + OFF_SZ);
    int*   sMask = (int*)  (smraw + OFF_MASK);
    uint8_t* sRel = (uint8_t*)(smraw + OFF_REL);

    const int qt = blockIdx.x, h = blockIdx.y, b = blockIdx.z;
    const int i0 = qt * 16;
    const int tid  = threadIdx.x;
    const int lane = tid & 31;
    const int warp = tid >> 5;
    const int is64 = g_arc_is64;
    const size_t bh     = (size_t)b*H_ + h;
    const size_t qrow0  = bh*S_ + i0;
    const size_t krow0  = bh*S_;
    const size_t kvbase = bh*S_*HD_;

    for (int i = tid; i < 16*NRELV; i += 256) {
        sB[i] = g_bias[qrow0*NRELV + i];
        sW[i] = 0.f;
    }
    for (int i = tid; i < S_; i += 256) sMask[i] = mask[b*S_ + i];
    __syncthreads();

    // ---- Q A-fragments from pre-split global ----
    uint32_t qah[4][4], qal[4][4];
    {
        const int qr = lane >> 2;
        const int qc = (lane & 3) * 2;
        #pragma unroll
        for (int kk = 0; kk < 4; kk++) {
            const size_t r0o = (qrow0 + qr)*128     + kk*16 + qc;
            const size_t r1o = (qrow0 + qr + 8)*128 + kk*16 + qc;
            qah[kk][0] = *(const uint32_t*)&g_qkhi[r0o];
            qah[kk][1] = *(const uint32_t*)&g_qkhi[r1o];
            qah[kk][2] = *(const uint32_t*)&g_qkhi[r0o + 8];
            qah[kk][3] = *(const uint32_t*)&g_qkhi[r1o + 8];
            qal[kk][0] = *(const uint32_t*)&g_qklo[r0o];
            qal[kk][1] = *(const uint32_t*)&g_qklo[r1o];
            qal[kk][2] = *(const uint32_t*)&g_qklo[r0o + 8];
            qal[kk][3] = *(const uint32_t*)&g_qklo[r1o + 8];
        }
    }

    // tile copy mapping: 2 threads/row, each a contiguous 32-elem half
    const int copyrow = tid >> 1;
    const int chalf   = (tid & 1) * 32;

    // ---- pass 1: S = Q K^T via mma (K cols 64-127 of g_qk) ----
    for (int jt = 0; jt < 4; jt++) {
        const int j0 = jt * 128;
        {
            const size_t src = (krow0 + j0 + copyrow)*128 + 64 + chalf;
            #pragma unroll
            for (int u = 0; u < 4; u++) {
                *(uint4*)&sKhi[copyrow*72 + chalf + u*8] = *(const uint4*)(g_qkhi + src + u*8);
                *(uint4*)&sKlo[copyrow*72 + chalf + u*8] = *(const uint4*)(g_qklo + src + u*8);
            }
        }
        __syncthreads();

        float c[2][4] = {{0,0,0,0},{0,0,0,0}};
        const int nw = warp * 16;
        #pragma unroll
        for (int kk = 0; kk < 4; kk++) {
            #pragma unroll
            for (int nt = 0; nt < 2; nt++) {
                const int j = nw + nt*8 + (lane >> 2);
                const int d = kk*16 + (lane & 3)*2;
                uint32_t bh0 = *(uint32_t*)&sKhi[j*72 + d];
                uint32_t bh1 = *(uint32_t*)&sKhi[j*72 + d + 8];
                uint32_t bl0 = *(uint32_t*)&sKlo[j*72 + d];
                uint32_t bl1 = *(uint32_t*)&sKlo[j*72 + d + 8];
                mma16816(c[nt], qah[kk], bh0, bh1);
                mma16816(c[nt], qah[kk], bl0, bl1);
                mma16816(c[nt], qal[kk], bh0, bh1);
            }
        }
        #pragma unroll
        for (int nt = 0; nt < 2; nt++) {
            const int col = j0 + nw + nt*8 + 2*(lane & 3);
            const int r   = lane >> 2;
            *(float2*)&sS[r*SSTR + col]     = make_float2(c[nt][0], c[nt][1]);
            *(float2*)&sS[(r+8)*SSTR + col] = make_float2(c[nt][2], c[nt][3]);
        }
        __syncthreads();
    }

    // ---- relation bias + scale + mask (cache rel in smem) ----
    const size_t arcbase = ((size_t)b*S_ + i0)*S_;
    for (int idx = tid; idx < 16*S_; idx += 256) {
        int i = idx >> 9, j = idx & (S_-1);
        int rel = arc_at(arc, is64, arcbase + (size_t)i*S_ + j);
        sRel[idx] = (uint8_t)rel;
        float s = (sS[i*SSTR + j] + sB[i*NRELV + rel]) * 0.125f;
        if (sMask[j] == 0) s = -1e30f;
        sS[i*SSTR + j] = s;
    }
    __syncthreads();

    // ---- softmax ----
    #pragma unroll
    for (int rr = 0; rr < 2; rr++) {
        int row = warp*2 + rr;
        float m = -3.4e38f;
        for (int j = lane; j < S_; j += 32) m = fmaxf(m, sS[row*SSTR + j]);
        #pragma unroll
        for (int o = 16; o; o >>= 1) m = fmaxf(m, __shfl_xor_sync(0xffffffffu, m, o));
        float z = 0.f;
        for (int j = lane; j < S_; j += 32) {
            float p = __expf(sS[row*SSTR + j] - m);
            sS[row*SSTR + j] = p;
            z += p;
        }
        #pragma unroll
        for (int o = 16; o; o >>= 1) z += __shfl_xor_sync(0xffffffffu, z, o);
        if (lane == 0) sZ[row] = z;
    }
    __syncthreads();

    // ---- relation binning (rel from smem cache) ----
    for (int idx = tid; idx < 16*S_; idx += 256) {
        int i = idx >> 9, j = idx & (S_-1);
        atomicAdd(&sW[i*NRELV + sRel[idx]], sS[i*SSTR + j]);
    }
    __syncthreads();

    // ---- pass 2: ctx = P V via mma ----
    float c2[8][4];
    #pragma unroll
    for (int nt = 0; nt < 8; nt++)
        #pragma unroll
        for (int j = 0; j < 4; j++) c2[nt][j] = 0.f;

    const uint32_t vhiBase = (uint32_t)__cvta_generic_to_shared(sKhi);
    const uint32_t vloBase = (uint32_t)__cvta_generic_to_shared(sKlo);
    for (int jt = 0; jt < 4; jt++) {
        {
            const size_t src = kvbase + (size_t)(jt*128 + copyrow)*HD_ + chalf;
            #pragma unroll
            for (int u = 0; u < 4; u++) {
                *(uint4*)&sKhi[copyrow*72 + chalf + u*8] = *(const uint4*)(g_vhi + src + u*8);
                *(uint4*)&sKlo[copyrow*72 + chalf + u*8] = *(const uint4*)(g_vlo + src + u*8);
            }
        }
        __syncthreads();

        const int jb = jt*128 + warp*16;
        uint32_t pah[4], pal[4];
        {
            const int pr = lane >> 2;
            const int pc = (lane & 3) * 2;
            float2 x0 = *(float2*)&sS[pr*SSTR     + jb + pc];
            float2 x1 = *(float2*)&sS[(pr+8)*SSTR + jb + pc];
            float2 x2 = *(float2*)&sS[pr*SSTR     + jb + pc + 8];
            float2 x3 = *(float2*)&sS[(pr+8)*SSTR + jb + pc + 8];
            split2(x0.x, x0.y, pah[0], pal[0]);
            split2(x1.x, x1.y, pah[1], pal[1]);
            split2(x2.x, x2.y, pah[2], pal[2]);
            split2(x3.x, x3.y, pah[3], pal[3]);
        }
        const uint32_t rowoff = (uint32_t)(warp*16 + (lane & 15)) * 144;
        #pragma unroll
        for (int nt = 0; nt < 8; nt++) {
            uint32_t bh0, bh1, bl0, bl1;
            ldsm_x2_trans(vhiBase + rowoff + nt*16, bh0, bh1);
            ldsm_x2_trans(vloBase + rowoff + nt*16, bl0, bl1);
            mma16816(c2[nt], pah, bh0, bh1);
            mma16816(c2[nt], pah, bl0, bl1);
            mma16816(c2[nt], pal, bh0, bh1);
        }
        __syncthreads();
    }

    // ---- cross-warp reduction of PV partials (reuse sS) + load Ev ----
    {
        float* red = sS;
        const int r = lane >> 2;
        #pragma unroll
        for (int nt = 0; nt < 8; nt++) {
            const int col = nt*8 + 2*(lane & 3);
            red[warp*1024 + r*64 + col]       = c2[nt][0];
            red[warp*1024 + r*64 + col + 1]   = c2[nt][1];
            red[warp*1024 + (r+8)*64 + col]   = c2[nt][2];
            red[warp*1024 + (r+8)*64 + col+1] = c2[nt][3];
        }
    }
    for (int i = tid; i < NRELV*HD_; i += 256) sEv[i] = Ev[i];
    __syncthreads();

    // ---- final: reduce, + wrel@Ev, /Z, store ctx as bf16 hi/lo ----
    {
        const int row = tid >> 4;            // 0..15
        const int e0  = (tid & 15) * 4;      // 0..60
        float4 acc = make_float4(0,0,0,0);
        #pragma unroll
        for (int w = 0; w < 8; w++) {
            float4 p = *(float4*)&sS[w*1024 + row*64 + e0];
            acc.x += p.x; acc.y += p.y; acc.z += p.z; acc.w += p.w;
        }
        const float* wrow = &sW[row*NRELV];
        for (int rel = 0; rel < NRELV; rel++) {
            float wv = wrow[rel];
            float4 ev = *(float4*)&sEv[rel*64 + e0];
            acc.x += wv*ev.x; acc.y += wv*ev.y; acc.z += wv*ev.z; acc.w += wv*ev.w;
        }
        const float rz = 1.f / sZ[row];
        acc.x *= rz; acc.y *= rz; acc.z *= rz; acc.w *= rz;

        uint32_t h0, l0, h1, l1;
        split2(acc.x, acc.y, h0, l0);
        split2(acc.z, acc.w, h1, l1);
        const size_t o = ((size_t)(b*S_ + i0 + row))*D_ + h*HD_ + e0;
        *(uint2*)&g_chi[o] = make_uint2(h0, h1);
        *(uint2*)&g_clo[o] = make_uint2(l0, l1);
    }
}

// ---------------- launch --------------------------------------------------------
extern "C" void kernel_launch(void* const* d_in, const int* in_sizes, int n_in,
                              void* d_out, int out_size)
{
    (void)in_sizes; (void)n_in; (void)out_size;
    const float* query = (const float*)d_in[0];
    const float* key_  = (const float*)d_in[1];
    const float* value = (const float*)d_in[2];
    const int*   mask  = (const int*)d_in[3];
    const void*  arc   = d_in[4];
    const float* bq = (const float*)d_in[6];
    const float* bk = (const float*)d_in[8];
    const float* bv = (const float*)d_in[10];
    const float* bo = (const float*)d_in[12];
    const float* Ek = (const float*)d_in[13];
    const float* Eq = (const float*)d_in[14];
    const float* Ev = (const float*)d_in[15];
    float* out = (float*)d_out;

    cudaFuncSetAttribute(attn_kernel, cudaFuncAttributeMaxDynamicSharedMemorySize, SMEM_ATTN);

    __nv_bfloat16 *xhi, *xlo, *whi, *wlo;
    cudaGetSymbolAddress((void**)&xhi, g_xhi);
    cudaGetSymbolAddress((void**)&xlo, g_xlo);
    cudaGetSymbolAddress((void**)&whi, g_whi);
    cudaGetSymbolAddress((void**)&wlo, g_wlo);

    detect_kernel<<<1, 256>>>((const int*)arc);

    SplitArgs sa;
    const float* srcs[7] = {query, key_, value,
                            (const float*)d_in[5], (const float*)d_in[7],
                            (const float*)d_in[9], (const float*)d_in[11]};
    for (int i = 0; i < 7; i++) {
        sa.src[i] = srcs[i];
        if (i < 3) {
            sa.hi[i] = xhi + (size_t)i*XN;
            sa.lo[i] = xlo + (size_t)i*XN;
            sa.n[i]  = XN;
        } else {
            sa.hi[i] = whi + (size_t)(i-3)*WN;
            sa.lo[i] = wlo + (size_t)(i-3)*WN;
            sa.n[i]  = WN;
        }
    }
    split_kernel<<<dim3((XN/4 + 255)/256, 7), 256>>>(sa);
    ebuild_kernel<<<(EROWS*128 + 255)/256, 256>>>(Ek, Eq);

    dim3 qkvGrid(D_/BN, (B_*S_)/BM, 3);
    mma_gemm_kernel<0><<<qkvGrid, 256>>>(bq, bk, bv, nullptr);

    bias_mma_kernel<<<dim3(4, H_, B_), 256>>>();
    attn_kernel<<<dim3(S_/16, H_, B_), 256, SMEM_ATTN>>>(mask, arc, Ev);

    dim3 oGrid(D_/BN, (B_*S_)/BM, 1);
    mma_gemm_kernel<1><<<oGrid, 256>>>(bo, nullptr, nullptr, out);
}

// round 6
// speedup vs baseline: 3.0800x; 1.0804x over previous
#include <cuda_runtime.h>
#include <cuda_bf16.h>
#include <cstdint>
#include <cstddef>

#define B_    4
#define S_    512
#define D_    768
#define H_    12
#define HD_   64
#define NRELV 101
#define EROWS 112
#define XN    (B_*S_*D_)
#define WN    (D_*D_)

#define BM    128
#define BN    128
#define BK    32
#define LDSB  40           // bf16 stride (80B) -> ldmatrix conflict-free
#define GSTAGE 40960       // bytes per gemm pipeline stage (4 arrays x 128 x 80B)

// ---------------- scratch ------------------------------------------------------
__device__ __nv_bfloat16 g_qkhi[(size_t)B_*H_*S_*128], g_qklo[(size_t)B_*H_*S_*128];
__device__ __nv_bfloat16 g_vhi[XN], g_vlo[XN];
__device__ __nv_bfloat16 g_xhi[3*XN], g_xlo[3*XN];
__device__ __nv_bfloat16 g_whi[4*WN], g_wlo[4*WN];
__device__ __nv_bfloat16 g_chi[XN], g_clo[XN];
__device__ __nv_bfloat16 g_ehi[EROWS*128], g_elo[EROWS*128];
__device__ float g_bias[(size_t)B_*H_*S_*NRELV];
__device__ int   g_arc_is64;

// ---------------- helpers ------------------------------------------------------
__device__ __forceinline__ void split2(float a, float b, uint32_t& hi, uint32_t& lo)
{
    __nv_bfloat16 h0 = __float2bfloat16(a);
    __nv_bfloat16 h1 = __float2bfloat16(b);
    __nv_bfloat16 l0 = __float2bfloat16(a - __bfloat162float(h0));
    __nv_bfloat16 l1 = __float2bfloat16(b - __bfloat162float(h1));
    hi = (uint32_t)*(unsigned short*)&h0 | ((uint32_t)*(unsigned short*)&h1 << 16);
    lo = (uint32_t)*(unsigned short*)&l0 | ((uint32_t)*(unsigned short*)&l1 << 16);
}

__device__ __forceinline__ void ldsm_x4(uint32_t addr, uint32_t& r0, uint32_t& r1,
                                        uint32_t& r2, uint32_t& r3)
{
    asm volatile("ldmatrix.sync.aligned.m8n8.x4.shared.b16 {%0,%1,%2,%3}, [%4];"
                 : "=r"(r0), "=r"(r1), "=r"(r2), "=r"(r3) : "r"(addr));
}

__device__ __forceinline__ void ldsm_x2_trans(uint32_t addr, uint32_t& r0, uint32_t& r1)
{
    asm volatile("ldmatrix.sync.aligned.m8n8.x2.trans.shared.b16 {%0,%1}, [%2];"
                 : "=r"(r0), "=r"(r1) : "r"(addr));
}

__device__ __forceinline__ void mma16816(float* c, const uint32_t* a,
                                         uint32_t b0, uint32_t b1)
{
    asm volatile(
        "mma.sync.aligned.m16n8k16.row.col.f32.bf16.bf16.f32 "
        "{%0,%1,%2,%3}, {%4,%5,%6,%7}, {%8,%9}, {%0,%1,%2,%3};"
        : "+f"(c[0]), "+f"(c[1]), "+f"(c[2]), "+f"(c[3])
        : "r"(a[0]), "r"(a[1]), "r"(a[2]), "r"(a[3]), "r"(b0), "r"(b1));
}

__device__ __forceinline__ void cp16(uint32_t dst, const void* src)
{
    asm volatile("cp.async.ca.shared.global [%0], [%1], 16;" :: "r"(dst), "l"(src));
}

// ---------------- graph_arc dtype detection ------------------------------------
__global__ void detect_kernel(const int* __restrict__ arc32)
{
    __shared__ int cnt;
    if (threadIdx.x == 0) cnt = 0;
    __syncthreads();
    int local = 0;
    for (int i = threadIdx.x; i < 1024; i += blockDim.x)
        if (arc32[2*i + 1] != 0) local++;
    if (local) atomicAdd(&cnt, local);
    __syncthreads();
    if (threadIdx.x == 0) g_arc_is64 = (cnt == 0) ? 1 : 0;
}

__device__ __forceinline__ int arc_at(const void* arc, int is64, size_t idx)
{
    if (is64) return (int)(((const long long*)arc)[idx]);
    return ((const int*)arc)[idx];
}

// ---------------- prepass: fp32 -> bf16 hi/lo split -----------------------------
struct SplitArgs {
    const float*   src[7];
    __nv_bfloat16* hi[7];
    __nv_bfloat16* lo[7];
    int            n[7];
};

__global__ void __launch_bounds__(256)
split_kernel(SplitArgs a)
{
    const int w = blockIdx.y;
    const int n = a.n[w];
    const int i = (blockIdx.x * 256 + threadIdx.x) * 4;
    if (i >= n) return;
    float4 v = *(const float4*)(a.src[w] + i);
    uint32_t h0, l0, h1, l1;
    split2(v.x, v.y, h0, l0);
    split2(v.z, v.w, h1, l1);
    *(uint2*)(a.hi[w] + i) = make_uint2(h0, h1);
    *(uint2*)(a.lo[w] + i) = make_uint2(l0, l1);
}

__global__ void __launch_bounds__(256)
ebuild_kernel(const float* __restrict__ Ek, const float* __restrict__ Eq)
{
    int idx = blockIdx.x * 256 + threadIdx.x;
    if (idx >= EROWS*128) return;
    int row = idx >> 7, col = idx & 127;
    float v = 0.f;
    if (row < NRELV) v = (col < 64) ? Ek[row*64 + col] : Eq[row*64 + col - 64];
    __nv_bfloat16 hv = __float2bfloat16(v);
    __nv_bfloat16 lv = __float2bfloat16(v - __bfloat162float(hv));
    g_ehi[idx] = hv;
    g_elo[idx] = lv;
}

// ---------------- tensor-core GEMM, cp.async 2-stage pipeline -------------------
// stage layout (bytes): Xhi@0  Xlo@10240  Whi@20480  Wlo@30720 ; 2 stages.
template<int MODE>
__global__ void __launch_bounds__(256, 2)
mma_gemm_kernel(const float* __restrict__ bias0, const float* __restrict__ bias1,
                const float* __restrict__ bias2, float* __restrict__ out1)
{
    extern __shared__ char gsm[];
    const uint32_t smemBase = (uint32_t)__cvta_generic_to_shared(gsm);

    const int z = (MODE == 0) ? blockIdx.z : 0;
    const __nv_bfloat16 *Xhi, *Xlo, *Whi, *Wlo;
    const float* bias;
    if (MODE == 0) {
        Xhi = g_xhi + (size_t)z*XN;  Xlo = g_xlo + (size_t)z*XN;
        Whi = g_whi + (size_t)z*WN;  Wlo = g_wlo + (size_t)z*WN;
        bias = (z == 0) ? bias0 : (z == 1) ? bias1 : bias2;
    } else {
        Xhi = g_chi;  Xlo = g_clo;
        Whi = g_whi + (size_t)3*WN;  Wlo = g_wlo + (size_t)3*WN;
        bias = bias0;
    }

    const int tid  = threadIdx.x;
    const int lane = tid & 31;
    const int warp = tid >> 5;
    const int wm   = warp & 3;
    const int wn   = warp >> 2;
    const int m0   = blockIdx.y * BM;
    const int n0   = blockIdx.x * BN;

    float acc[2][8][4];
    #pragma unroll
    for (int mt = 0; mt < 2; mt++)
        #pragma unroll
        for (int nt = 0; nt < 8; nt++)
            #pragma unroll
            for (int j = 0; j < 4; j++) acc[mt][nt][j] = 0.f;

    // fragment smem offsets within a stage (bytes)
    const int mat = lane >> 3, mr = lane & 7;
    const uint32_t aOffHi = (uint32_t)((wm*32 + (mat & 1)*8 + mr)*80 + ((mat >> 1)*8)*2);
    const uint32_t bOffHi = 20480u + (uint32_t)((wn*64 + (mat >> 1)*8 + mr)*80 + ((mat & 1)*8)*2);

    const int ldrow = tid >> 1;
    const int ldq   = (tid & 1) * 2;
    const uint32_t xDst = (uint32_t)(ldrow*80 + ldq*16);
    const uint32_t wDst = 20480u + xDst;

    // prologue: load stage 0 (k0 = 0)
    #pragma unroll
    for (int u = 0; u < 2; u++) {
        const size_t xo = (size_t)(m0 + ldrow)*D_ + (ldq + u)*8;
        const size_t wo = (size_t)(n0 + ldrow)*D_ + (ldq + u)*8;
        cp16(smemBase + xDst + u*16,          Xhi + xo);
        cp16(smemBase + 10240 + xDst + u*16,  Xlo + xo);
        cp16(smemBase + wDst + u*16,          Whi + wo);
        cp16(smemBase + 10240 + wDst + u*16,  Wlo + wo);
    }
    asm volatile("cp.async.commit_group;");

    const int NK = D_ / BK;   // 24
    for (int kt = 0; kt < NK; kt++) {
        asm volatile("cp.async.wait_group 0;");
        __syncthreads();

        if (kt + 1 < NK) {
            const uint32_t sb2 = smemBase + (uint32_t)(((kt + 1) & 1) * GSTAGE);
            const int k0 = (kt + 1) * BK;
            #pragma unroll
            for (int u = 0; u < 2; u++) {
                const size_t xo = (size_t)(m0 + ldrow)*D_ + k0 + (ldq + u)*8;
                const size_t wo = (size_t)(n0 + ldrow)*D_ + k0 + (ldq + u)*8;
                cp16(sb2 + xDst + u*16,          Xhi + xo);
                cp16(sb2 + 10240 + xDst + u*16,  Xlo + xo);
                cp16(sb2 + wDst + u*16,          Whi + wo);
                cp16(sb2 + 10240 + wDst + u*16,  Wlo + wo);
            }
        }
        asm volatile("cp.async.commit_group;");

        const uint32_t sb = smemBase + (uint32_t)((kt & 1) * GSTAGE);
        #pragma unroll
        for (int ks = 0; ks < 2; ks++) {
            const uint32_t ko = ks * 32;
            uint32_t ah[2][4], al[2][4];
            #pragma unroll
            for (int mt = 0; mt < 2; mt++) {
                const uint32_t mo = mt * 1280;
                ldsm_x4(sb + aOffHi + mo + ko,          ah[mt][0], ah[mt][1], ah[mt][2], ah[mt][3]);
                ldsm_x4(sb + aOffHi + 10240 + mo + ko,  al[mt][0], al[mt][1], al[mt][2], al[mt][3]);
            }
            #pragma unroll
            for (int pr = 0; pr < 4; pr++) {
                const uint32_t po = pr * 1280;
                uint32_t bh[4], bl[4];
                ldsm_x4(sb + bOffHi + po + ko,          bh[0], bh[1], bh[2], bh[3]);
                ldsm_x4(sb + bOffHi + 10240 + po + ko,  bl[0], bl[1], bl[2], bl[3]);
                #pragma unroll
                for (int h2 = 0; h2 < 2; h2++) {
                    const int nt = pr*2 + h2;
                    #pragma unroll
                    for (int mt = 0; mt < 2; mt++) {
                        mma16816(acc[mt][nt], ah[mt], bh[h2*2], bh[h2*2+1]);
                        mma16816(acc[mt][nt], ah[mt], bl[h2*2], bl[h2*2+1]);
                        mma16816(acc[mt][nt], al[mt], bh[h2*2], bh[h2*2+1]);
                    }
                }
            }
        }
    }

    // ---- epilogue ----
    const int gid = lane >> 2, tig = lane & 3;
    #pragma unroll
    for (int mt = 0; mt < 2; mt++) {
        const int rbase = m0 + wm*32 + mt*16 + gid;
        #pragma unroll
        for (int nt = 0; nt < 8; nt++) {
            const int col = n0 + wn*64 + nt*8 + tig*2;
            const float b0v = bias[col], b1v = bias[col+1];
            float v00 = acc[mt][nt][0] + b0v;
            float v01 = acc[mt][nt][1] + b1v;
            float v10 = acc[mt][nt][2] + b0v;
            float v11 = acc[mt][nt][3] + b1v;
            if (MODE == 0) {
                const int hh = col >> 6, e = col & 63;
                #pragma unroll
                for (int half = 0; half < 2; half++) {
                    const int r = rbase + half*8;
                    const int b = r >> 9, s = r & (S_-1);
                    const size_t rowb = (size_t)(b*H_ + hh)*S_ + s;
                    const float va = half ? v10 : v00;
                    const float vb = half ? v11 : v01;
                    uint32_t hi, lo; split2(va, vb, hi, lo);
                    if (z == 0) {
                        *(uint32_t*)&g_qkhi[rowb*128 + e] = hi;
                        *(uint32_t*)&g_qklo[rowb*128 + e] = lo;
                    } else if (z == 1) {
                        *(uint32_t*)&g_qkhi[rowb*128 + 64 + e] = hi;
                        *(uint32_t*)&g_qklo[rowb*128 + 64 + e] = lo;
                    } else {
                        *(uint32_t*)&g_vhi[rowb*64 + e] = hi;
                        *(uint32_t*)&g_vlo[rowb*64 + e] = lo;
                    }
                }
            } else {
                out1[(size_t)rbase*D_ + col]       = v00;
                out1[(size_t)rbase*D_ + col + 1]   = v01;
                out1[(size_t)(rbase+8)*D_ + col]   = v10;
                out1[(size_t)(rbase+8)*D_ + col+1] = v11;
            }
        }
    }
}

// ---------------- bias table via tensor cores -----------------------------------
__global__ void __launch_bounds__(256, 1)
bias_mma_kernel()
{
    __shared__ __nv_bfloat16 sAhi[128][LDSB], sAlo[128][LDSB];
    __shared__ __nv_bfloat16 sBhi[EROWS][LDSB], sBlo[EROWS][LDSB];

    const int rt = blockIdx.x;
    const int h  = blockIdx.y, b = blockIdx.z;
    const size_t bh = (size_t)b*H_ + h;
    const size_t abase = (bh*S_ + rt*128) * 128;

    const int tid  = threadIdx.x;
    const int lane = tid & 31;
    const int warp = tid >> 5;

    float acc[14][4];
    #pragma unroll
    for (int nt = 0; nt < 14; nt++)
        #pragma unroll
        for (int j = 0; j < 4; j++) acc[nt][j] = 0.f;

    const int mat = lane >> 3, mr = lane & 7;
    const int a_row = (mat & 1) * 8 + mr;
    const int a_k   = (mat >> 1) * 8;
    const uint32_t aHi = (uint32_t)__cvta_generic_to_shared(&sAhi[warp*16 + a_row][a_k]);
    const uint32_t aLo = (uint32_t)__cvta_generic_to_shared(&sAlo[warp*16 + a_row][a_k]);
    const int b_row = (mat >> 1) * 8 + mr;
    const int b_k   = (mat & 1) * 8;
    const uint32_t bHi = (uint32_t)__cvta_generic_to_shared(&sBhi[b_row][b_k]);
    const uint32_t bLo = (uint32_t)__cvta_generic_to_shared(&sBlo[b_row][b_k]);

    for (int k0 = 0; k0 < 128; k0 += BK) {
        {
            const int arow = tid >> 1;
            const int acol = (tid & 1) * 16;
            const size_t src = abase + (size_t)arow*128 + k0 + acol;
            uint4 h0 = *(const uint4*)(g_qkhi + src);
            uint4 h1 = *(const uint4*)(g_qkhi + src + 8);
            uint4 l0 = *(const uint4*)(g_qklo + src);
            uint4 l1 = *(const uint4*)(g_qklo + src + 8);
            __syncthreads();
            *(uint4*)&sAhi[arow][acol]     = h0;
            *(uint4*)&sAhi[arow][acol + 8] = h1;
            *(uint4*)&sAlo[arow][acol]     = l0;
            *(uint4*)&sAlo[arow][acol + 8] = l1;
        }
        if (tid < EROWS*2) {
            const int brow = tid >> 1;
            const int bcol = (tid & 1) * 16;
            const size_t src = (size_t)brow*128 + k0 + bcol;
            *(uint4*)&sBhi[brow][bcol]     = *(const uint4*)(g_ehi + src);
            *(uint4*)&sBhi[brow][bcol + 8] = *(const uint4*)(g_ehi + src + 8);
            *(uint4*)&sBlo[brow][bcol]     = *(const uint4*)(g_elo + src);
            *(uint4*)&sBlo[brow][bcol + 8] = *(const uint4*)(g_elo + src + 8);
        }
        __syncthreads();

        #pragma unroll
        for (int ks = 0; ks < 2; ks++) {
            const uint32_t ko = ks * 32;
            uint32_t ah[4], al[4];
            ldsm_x4(aHi + ko, ah[0], ah[1], ah[2], ah[3]);
            ldsm_x4(aLo + ko, al[0], al[1], al[2], al[3]);
            #pragma unroll
            for (int pr = 0; pr < 7; pr++) {
                const uint32_t po = pr * (16 * LDSB * 2);
                uint32_t bhf[4], blf[4];
                ldsm_x4(bHi + po + ko, bhf[0], bhf[1], bhf[2], bhf[3]);
                ldsm_x4(bLo + po + ko, blf[0], blf[1], blf[2], blf[3]);
                #pragma unroll
                for (int h2 = 0; h2 < 2; h2++) {
                    const int nt = pr*2 + h2;
                    mma16816(acc[nt], ah, bhf[h2*2], bhf[h2*2+1]);
                    mma16816(acc[nt], ah, blf[h2*2], blf[h2*2+1]);
                    mma16816(acc[nt], al, bhf[h2*2], bhf[h2*2+1]);
                }
            }
        }
        __syncthreads();
    }

    const int gid = lane >> 2, tig = lane & 3;
    const int row0 = rt*128 + warp*16 + gid;
    #pragma unroll
    for (int nt = 0; nt < 14; nt++) {
        const int col = nt*8 + tig*2;
        #pragma unroll
        for (int half = 0; half < 2; half++) {
            const int row = row0 + half*8;
            const size_t o = (bh*S_ + row)*NRELV;
            const float v0 = acc[nt][half*2];
            const float v1 = acc[nt][half*2+1];
            if (col < NRELV)     g_bias[o + col]     = v0;
            if (col + 1 < NRELV) g_bias[o + col + 1] = v1;
        }
    }
}

// ---------------- fused attention: QT=32 rows, 512 threads ----------------------
#define QT    32
#define SSTR  520
#define OFF_SS    0                       // 32*520*4 = 66560
#define OFF_KHI   66560                   // 128*72*2 = 18432
#define OFF_KLO   84992                   // -> 103424
#define OFF_EV    66560                   // Ev fp32 101*64 (reuses K region)
#define OFF_SB    103424                  // 32*101*4 = 12928
#define OFF_SW    116352                  // 12928
#define OFF_SZ    129280                  // 128
#define OFF_MASK  129408                  // 2048
#define OFF_REL   131456                  // 32*512 u8 = 16384
#define SMEM_ATTN 147840

__global__ void __launch_bounds__(512, 1)
attn_kernel(const int* __restrict__ mask, const void* __restrict__ arc,
            const float* __restrict__ Ev)
{
    extern __shared__ char smraw[];
    float* sS    = (float*)(smraw + OFF_SS);
    __nv_bfloat16* sKhi = (__nv_bfloat16*)(smraw + OFF_KHI);
    __nv_bfloat16* sKlo = (__nv_bfloat16*)(smraw + OFF_KLO);
    float* sEv   = (float*)(smraw + OFF_EV);
    float* sB    = (float*)(smraw + OFF_SB);
    float* sW    = (float*)(smraw + OFF_SW);
    float* sZ    = (float*)(smraw + OFF_SZ);
    int*   sMask = (int*)  (smraw + OFF_MASK);
    uint8_t* sRel = (uint8_t*)(smraw + OFF_REL);

    const int qt = blockIdx.x, h = blockIdx.y, b = blockIdx.z;
    const int i0 = qt * QT;
    const int tid  = threadIdx.x;
    const int lane = tid & 31;
    const int warp = tid >> 5;        // 0..15
    const int mt   = warp >> 3;       // m-tile 0/1 (16 rows each)
    const int wj   = warp & 7;        // j-slice within 128-tile
    const int is64 = g_arc_is64;
    const size_t bh    = (size_t)b*H_ + h;
    const size_t qrow0 = bh*S_ + i0;
    const size_t krow0 = bh*S_;
    const size_t vbase = bh*S_*HD_;

    for (int i = tid; i < QT*NRELV; i += 512) {
        sB[i] = g_bias[qrow0*NRELV + i];
        sW[i] = 0.f;
    }
    for (int i = tid; i < S_; i += 512) sMask[i] = mask[b*S_ + i];
    __syncthreads();

    // ---- Q A-fragments for this warp's m-tile ----
    uint32_t qah[4][4], qal[4][4];
    {
        const int qr = lane >> 2;
        const int qc = (lane & 3) * 2;
        const size_t qm = qrow0 + mt*16;
        #pragma unroll
        for (int kk = 0; kk < 4; kk++) {
            const size_t r0o = (qm + qr)*128     + kk*16 + qc;
            const size_t r1o = (qm + qr + 8)*128 + kk*16 + qc;
            qah[kk][0] = *(const uint32_t*)&g_qkhi[r0o];
            qah[kk][1] = *(const uint32_t*)&g_qkhi[r1o];
            qah[kk][2] = *(const uint32_t*)&g_qkhi[r0o + 8];
            qah[kk][3] = *(const uint32_t*)&g_qkhi[r1o + 8];
            qal[kk][0] = *(const uint32_t*)&g_qklo[r0o];
            qal[kk][1] = *(const uint32_t*)&g_qklo[r1o];
            qal[kk][2] = *(const uint32_t*)&g_qklo[r0o + 8];
            qal[kk][3] = *(const uint32_t*)&g_qklo[r1o + 8];
        }
    }

    // tile copy: 4 threads/row, contiguous 16-elem quarters
    const int copyrow = tid >> 2;           // 0..127
    const int cq      = (tid & 3) * 16;     // element offset

    // ---- pass 1: S = Q K^T via mma ----
    for (int jt = 0; jt < 4; jt++) {
        const int j0 = jt * 128;
        {
            const size_t src = (krow0 + j0 + copyrow)*128 + 64 + cq;
            #pragma unroll
            for (int u = 0; u < 2; u++) {
                *(uint4*)&sKhi[copyrow*72 + cq + u*8] = *(const uint4*)(g_qkhi + src + u*8);
                *(uint4*)&sKlo[copyrow*72 + cq + u*8] = *(const uint4*)(g_qklo + src + u*8);
            }
        }
        __syncthreads();

        float c[2][4] = {{0,0,0,0},{0,0,0,0}};
        const int nw = wj * 16;
        #pragma unroll
        for (int kk = 0; kk < 4; kk++) {
            #pragma unroll
            for (int nt = 0; nt < 2; nt++) {
                const int j = nw + nt*8 + (lane >> 2);
                const int d = kk*16 + (lane & 3)*2;
                uint32_t bh0 = *(uint32_t*)&sKhi[j*72 + d];
                uint32_t bh1 = *(uint32_t*)&sKhi[j*72 + d + 8];
                uint32_t bl0 = *(uint32_t*)&sKlo[j*72 + d];
                uint32_t bl1 = *(uint32_t*)&sKlo[j*72 + d + 8];
                mma16816(c[nt], qah[kk], bh0, bh1);
                mma16816(c[nt], qah[kk], bl0, bl1);
                mma16816(c[nt], qal[kk], bh0, bh1);
            }
        }
        #pragma unroll
        for (int nt = 0; nt < 2; nt++) {
            const int col = j0 + nw + nt*8 + 2*(lane & 3);
            const int r   = mt*16 + (lane >> 2);
            *(float2*)&sS[r*SSTR + col]     = make_float2(c[nt][0], c[nt][1]);
            *(float2*)&sS[(r+8)*SSTR + col] = make_float2(c[nt][2], c[nt][3]);
        }
        __syncthreads();
    }

    // ---- relation bias + scale + mask (cache rel) ----
    const size_t arcbase = ((size_t)b*S_ + i0)*S_;
    #pragma unroll 4
    for (int idx = tid; idx < QT*S_; idx += 512) {
        int i = idx >> 9, j = idx & (S_-1);
        int rel = arc_at(arc, is64, arcbase + (size_t)i*S_ + j);
        sRel[idx] = (uint8_t)rel;
        float s = (sS[i*SSTR + j] + sB[i*NRELV + rel]) * 0.125f;
        if (sMask[j] == 0) s = -1e30f;
        sS[i*SSTR + j] = s;
    }
    __syncthreads();

    // ---- softmax (unnormalized exp; Z per row) ----
    #pragma unroll
    for (int rr = 0; rr < 2; rr++) {
        int row = warp*2 + rr;
        float m = -3.4e38f;
        for (int j = lane; j < S_; j += 32) m = fmaxf(m, sS[row*SSTR + j]);
        #pragma unroll
        for (int o = 16; o; o >>= 1) m = fmaxf(m, __shfl_xor_sync(0xffffffffu, m, o));
        float z = 0.f;
        for (int j = lane; j < S_; j += 32) {
            float p = __expf(sS[row*SSTR + j] - m);
            sS[row*SSTR + j] = p;
            z += p;
        }
        #pragma unroll
        for (int o = 16; o; o >>= 1) z += __shfl_xor_sync(0xffffffffu, z, o);
        if (lane == 0) sZ[row] = z;
    }
    __syncthreads();

    // ---- relation binning ----
    for (int idx = tid; idx < QT*S_; idx += 512) {
        int i = idx >> 9, j = idx & (S_-1);
        atomicAdd(&sW[i*NRELV + sRel[idx]], sS[i*SSTR + j]);
    }
    __syncthreads();

    // ---- pass 2: ctx = P V via mma ----
    float c2[8][4];
    #pragma unroll
    for (int nt = 0; nt < 8; nt++)
        #pragma unroll
        for (int j = 0; j < 4; j++) c2[nt][j] = 0.f;

    const uint32_t vhiBase = (uint32_t)__cvta_generic_to_shared(sKhi);
    const uint32_t vloBase = (uint32_t)__cvta_generic_to_shared(sKlo);
    for (int jt = 0; jt < 4; jt++) {
        {
            const size_t src = vbase + (size_t)(jt*128 + copyrow)*HD_ + cq;
            #pragma unroll
            for (int u = 0; u < 2; u++) {
                *(uint4*)&sKhi[copyrow*72 + cq + u*8] = *(const uint4*)(g_vhi + src + u*8);
                *(uint4*)&sKlo[copyrow*72 + cq + u*8] = *(const uint4*)(g_vlo + src + u*8);
            }
        }
        __syncthreads();

        const int jb = jt*128 + wj*16;
        uint32_t pah[4], pal[4];
        {
            const int pr = mt*16 + (lane >> 2);
            const int pc = (lane & 3) * 2;
            float2 x0 = *(float2*)&sS[pr*SSTR     + jb + pc];
            float2 x1 = *(float2*)&sS[(pr+8)*SSTR + jb + pc];
            float2 x2 = *(float2*)&sS[pr*SSTR     + jb + pc + 8];
            float2 x3 = *(float2*)&sS[(pr+8)*SSTR + jb + pc + 8];
            split2(x0.x, x0.y, pah[0], pal[0]);
            split2(x1.x, x1.y, pah[1], pal[1]);
            split2(x2.x, x2.y, pah[2], pal[2]);
            split2(x3.x, x3.y, pah[3], pal[3]);
        }
        const uint32_t rowoff = (uint32_t)(wj*16 + (lane & 15)) * 144;
        #pragma unroll
        for (int nt = 0; nt < 8; nt++) {
            uint32_t bh0, bh1, bl0, bl1;
            ldsm_x2_trans(vhiBase + rowoff + nt*16, bh0, bh1);
            ldsm_x2_trans(vloBase + rowoff + nt*16, bl0, bl1);
            mma16816(c2[nt], pah, bh0, bh1);
            mma16816(c2[nt], pah, bl0, bl1);
            mma16816(c2[nt], pal, bh0, bh1);
        }
        __syncthreads();
    }

    // ---- PV partials to smem (reuse sS) + load Ev ----
    {
        float* red = sS;
        const int r = lane >> 2;
        #pragma unroll
        for (int nt = 0; nt < 8; nt++) {
            const int col = nt*8 + 2*(lane & 3);
            red[warp*1024 + r*64 + col]       = c2[nt][0];
            red[warp*1024 + r*64 + col + 1]   = c2[nt][1];
            red[warp*1024 + (r+8)*64 + col]   = c2[nt][2];
            red[warp*1024 + (r+8)*64 + col+1] = c2[nt][3];
        }
    }
    for (int i = tid; i < NRELV*HD_; i += 512) sEv[i] = Ev[i];
    __syncthreads();

    // ---- final: reduce 8 partials, + wrel@Ev, /Z, store ctx hi/lo ----
    {
        const int row = tid >> 4;            // 0..31
        const int e0  = (tid & 15) * 4;
        const int rmt = row >> 4, rl = row & 15;
        float4 acc = make_float4(0,0,0,0);
        #pragma unroll
        for (int w = 0; w < 8; w++) {
            float4 p = *(float4*)&sS[(rmt*8 + w)*1024 + rl*64 + e0];
            acc.x += p.x; acc.y += p.y; acc.z += p.z; acc.w += p.w;
        }
        const float* wrow = &sW[row*NRELV];
        for (int rel = 0; rel < NRELV; rel++) {
            float wv = wrow[rel];
            float4 ev = *(float4*)&sEv[rel*64 + e0];
            acc.x += wv*ev.x; acc.y += wv*ev.y; acc.z += wv*ev.z; acc.w += wv*ev.w;
        }
        const float rz = 1.f / sZ[row];
        acc.x *= rz; acc.y *= rz; acc.z *= rz; acc.w *= rz;

        uint32_t h0, l0, h1, l1;
        split2(acc.x, acc.y, h0, l0);
        split2(acc.z, acc.w, h1, l1);
        const size_t o = ((size_t)(b*S_ + i0 + row))*D_ + h*HD_ + e0;
        *(uint2*)&g_chi[o] = make_uint2(h0, h1);
        *(uint2*)&g_clo[o] = make_uint2(l0, l1);
    }
}

// ---------------- launch --------------------------------------------------------
extern "C" void kernel_launch(void* const* d_in, const int* in_sizes, int n_in,
                              void* d_out, int out_size)
{
    (void)in_sizes; (void)n_in; (void)out_size;
    const float* query = (const float*)d_in[0];
    const float* key_  = (const float*)d_in[1];
    const float* value = (const float*)d_in[2];
    const int*   mask  = (const int*)d_in[3];
    const void*  arc   = d_in[4];
    const float* bq = (const float*)d_in[6];
    const float* bk = (const float*)d_in[8];
    const float* bv = (const float*)d_in[10];
    const float* bo = (const float*)d_in[12];
    const float* Ek = (const float*)d_in[13];
    const float* Eq = (const float*)d_in[14];
    const float* Ev = (const float*)d_in[15];
    float* out = (float*)d_out;

    cudaFuncSetAttribute(attn_kernel, cudaFuncAttributeMaxDynamicSharedMemorySize, SMEM_ATTN);
    cudaFuncSetAttribute(mma_gemm_kernel<0>, cudaFuncAttributeMaxDynamicSharedMemorySize, 2*GSTAGE);
    cudaFuncSetAttribute(mma_gemm_kernel<1>, cudaFuncAttributeMaxDynamicSharedMemorySize, 2*GSTAGE);

    __nv_bfloat16 *xhi, *xlo, *whi, *wlo;
    cudaGetSymbolAddress((void**)&xhi, g_xhi);
    cudaGetSymbolAddress((void**)&xlo, g_xlo);
    cudaGetSymbolAddress((void**)&whi, g_whi);
    cudaGetSymbolAddress((void**)&wlo, g_wlo);

    detect_kernel<<<1, 256>>>((const int*)arc);

    SplitArgs sa;
    const float* srcs[7] = {query, key_, value,
                            (const float*)d_in[5], (const float*)d_in[7],
                            (const float*)d_in[9], (const float*)d_in[11]};
    for (int i = 0; i < 7; i++) {
        sa.src[i] = srcs[i];
        if (i < 3) {
            sa.hi[i] = xhi + (size_t)i*XN;
            sa.lo[i] = xlo + (size_t)i*XN;
            sa.n[i]  = XN;
        } else {
            sa.hi[i] = whi + (size_t)(i-3)*WN;
            sa.lo[i] = wlo + (size_t)(i-3)*WN;
            sa.n[i]  = WN;
        }
    }
    split_kernel<<<dim3((XN/4 + 255)/256, 7), 256>>>(sa);
    ebuild_kernel<<<(EROWS*128 + 255)/256, 256>>>(Ek, Eq);

    dim3 qkvGrid(D_/BN, (B_*S_)/BM, 3);
    mma_gemm_kernel<0><<<qkvGrid, 256, 2*GSTAGE>>>(bq, bk, bv, nullptr);

    bias_mma_kernel<<<dim3(4, H_, B_), 256>>>();
    attn_kernel<<<dim3(S_/QT, H_, B_), 512, SMEM_ATTN>>>(mask, arc, Ev);

    dim3 oGrid(D_/BN, (B_*S_)/BM, 1);
    mma_gemm_kernel<1><<<oGrid, 256, 2*GSTAGE>>>(bo, nullptr, nullptr, out);
}